// round 12
// baseline (speedup 1.0000x reference)
#include <cuda_runtime.h>
#include <cuda_fp16.h>
#include <math.h>

#define NBATCH 2
#define SEQ 2048
#define TT (NBATCH*SEQ)      /* 4096 tokens */
#define DIM 1024
#define NH 16
#define NKV 4
#define HD 64
#define KVD (NKV*HD)         /* 256 */
#define QKVD 1536            /* 1024 q + 256 k + 256 v */
#define NE 8
#define HID 2816
#define VOCAB 32000
#define NL 2
#define EPSF 1e-6f
#define MAXT 72

// ------------------------- fp32 scratch ------------------------------------
__device__ float g_h  [TT*DIM];
__device__ float g_xn [TT*DIM];
__device__ float g_qkv[TT*QKVD];
__device__ float g_b1 [TT*2*HID];
__device__ float g_b3 [TT*2*HID];
__device__ int   g_tope[TT*2];
__device__ float g_topw[TT*2];
__device__ int   g_cnt[NE];
__device__ int   g_scnt[NE];
__device__ int   g_seg[NE];
__device__ int   g_perm[TT*2];
__device__ float g_pwgt[TT*2];
__device__ int   g_te[MAXT], g_tp[MAXT], g_tv[MAXT];

// ------------------------- activation hi/lo half planes --------------------
__device__ __half g_xh[TT*2*HID], g_xl[TT*2*HID];

// ------------------------- KV half planes (K transposed per head) ----------
__device__ __half g_kth[NBATCH*NKV*HD*SEQ], g_ktl[NBATCH*NKV*HD*SEQ];
__device__ __half g_vh [NBATCH*NKV*SEQ*HD], g_vl [NBATCH*NKV*SEQ*HD];

// ------------------------- half hi/lo weight planes ------------------------
__device__ __half w_qkvh[NL*DIM*QKVD], w_qkvl[NL*DIM*QKVD];
__device__ __half w_oh[NL*DIM*DIM],   w_ol[NL*DIM*DIM];
__device__ __half w1h[NL*NE*DIM*HID], w1l[NL*NE*DIM*HID];
__device__ __half w3h[NL*NE*DIM*HID], w3l[NL*NE*DIM*HID];
__device__ __half w2h[NL*NE*HID*DIM], w2l[NL*NE*HID*DIM];
__device__ __half wouth[DIM*VOCAB],   woutl[DIM*VOCAB];

__device__ __forceinline__ float* bufsel(int id){
    switch(id){
        case 0: return g_h;
        case 1: return g_xn;
        case 2: return g_qkv;
        case 6: return g_b1;
        default: return g_b3;
    }
}
__device__ __forceinline__ __half* whsel(int id){
    switch(id){
        case 0:  return w_qkvh; case 1:  return w_qkvl;
        case 6:  return w_oh;   case 7:  return w_ol;
        case 8:  return w1h;    case 9:  return w1l;
        case 10: return w3h;    case 11: return w3l;
        case 12: return w2h;    case 13: return w2l;
        case 14: return wouth;  default: return woutl;
    }
}

// ------------------------- weight prep -------------------------------------
__global__ void cvt_k(const float* __restrict__ src, int hid, int lid, int n4){
    int i = blockIdx.x*256 + threadIdx.x;
    if(i >= n4) return;
    __half* hi = whsel(hid);
    __half* lo = whsel(lid);
    float4 v = ((const float4*)src)[i];
    __half h0=__float2half_rn(v.x), h1=__float2half_rn(v.y);
    __half h2=__float2half_rn(v.z), h3=__float2half_rn(v.w);
    __half l0=__float2half_rn(v.x-__half2float(h0));
    __half l1=__float2half_rn(v.y-__half2float(h1));
    __half l2=__float2half_rn(v.z-__half2float(h2));
    __half l3=__float2half_rn(v.w-__half2float(h3));
    ((__half2*)hi)[i*2  ] = __halves2half2(h0,h1);
    ((__half2*)hi)[i*2+1] = __halves2half2(h2,h3);
    ((__half2*)lo)[i*2  ] = __halves2half2(l0,l1);
    ((__half2*)lo)[i*2+1] = __halves2half2(l2,l3);
}

// pack wq/wk/wv columns into the combined [row][QKVD] planes
__global__ void cvtpack_k(const float* __restrict__ src, int Nsrc, int coloff, int n4){
    int i = blockIdx.x*256 + threadIdx.x;
    if(i >= n4) return;
    float4 v = ((const float4*)src)[i];
    int e = i*4;
    int row = e / Nsrc, col = e % Nsrc;
    size_t d = (size_t)row*QKVD + coloff + col;
    __half h0=__float2half_rn(v.x), h1=__float2half_rn(v.y);
    __half h2=__float2half_rn(v.z), h3=__float2half_rn(v.w);
    __half l0=__float2half_rn(v.x-__half2float(h0));
    __half l1=__float2half_rn(v.y-__half2float(h1));
    __half l2=__float2half_rn(v.z-__half2float(h2));
    __half l3=__float2half_rn(v.w-__half2float(h3));
    *(__half2*)&w_qkvh[d  ] = __halves2half2(h0,h1);
    *(__half2*)&w_qkvh[d+2] = __halves2half2(h2,h3);
    *(__half2*)&w_qkvl[d  ] = __halves2half2(l0,l1);
    *(__half2*)&w_qkvl[d+2] = __halves2half2(l2,l3);
}

// ------------------------- mma / ldmatrix / cp.async helpers ---------------
__device__ __forceinline__ void mma16816(float* c, const unsigned* a, const unsigned* b){
    asm volatile("mma.sync.aligned.m16n8k16.row.col.f32.f16.f16.f32 "
        "{%0,%1,%2,%3}, {%4,%5,%6,%7}, {%8,%9}, {%0,%1,%2,%3};"
        : "+f"(c[0]),"+f"(c[1]),"+f"(c[2]),"+f"(c[3])
        : "r"(a[0]),"r"(a[1]),"r"(a[2]),"r"(a[3]),"r"(b[0]),"r"(b[1]));
}
__device__ __forceinline__ void ldsm4(unsigned* r, unsigned addr){
    asm volatile("ldmatrix.sync.aligned.m8n8.x4.shared.b16 {%0,%1,%2,%3}, [%4];"
        : "=r"(r[0]),"=r"(r[1]),"=r"(r[2]),"=r"(r[3]) : "r"(addr));
}
__device__ __forceinline__ void ldsm2t(unsigned* r, unsigned addr){
    asm volatile("ldmatrix.sync.aligned.m8n8.x2.trans.shared.b16 {%0,%1}, [%2];"
        : "=r"(r[0]),"=r"(r[1]) : "r"(addr));
}
__device__ __forceinline__ void cpa16(unsigned dst, const void* src, unsigned sz){
    asm volatile("cp.async.cg.shared.global [%0], [%1], 16, %2;" :: "r"(dst), "l"(src), "r"(sz));
}
__device__ __forceinline__ void cpa_commit(){ asm volatile("cp.async.commit_group;"); }
template<int N>
__device__ __forceinline__ void cpa_wait(){ asm volatile("cp.async.wait_group %0;" :: "n"(N)); }

__device__ __forceinline__ void split2u(float a, float b, unsigned &hi, unsigned &lo){
    __half h0=__float2half_rn(a), h1=__float2half_rn(b);
    __half l0=__float2half_rn(a-__half2float(h0));
    __half l1=__float2half_rn(b-__half2float(h1));
    hi = (unsigned)__half_as_ushort(h0) | ((unsigned)__half_as_ushort(h1)<<16);
    lo = (unsigned)__half_as_ushort(l0) | ((unsigned)__half_as_ushort(l1)<<16);
}

#define BK 32
#define AST 40    /* A smem row stride (halfs) */
#define BST 136   /* B smem row stride (halfs) */
#define SA (128*AST)   /* 5120 halfs per A plane */
#define SB (BK*BST)    /* 4352 halfs per B plane */

// warp-tile compute over one BK tile
template<int TERMS>
__device__ __forceinline__ void tile_mma16(unsigned uAh, unsigned uAl, unsigned uBh, unsigned uBl,
                                           float acc[4][4][4], int wm, int wn, int lane){
    const int l15 = lane & 15;
    const int ahl = ((lane>>4)<<3);
#pragma unroll
    for(int ks=0;ks<2;ks++){
        unsigned bh[4][2], bl[4][2];
        unsigned brow = (unsigned)((ks*16 + l15)*BST + wn*32)*2;
#pragma unroll
        for(int nt=0;nt<4;nt++){
            ldsm2t(bh[nt], uBh + brow + nt*16);
            if(TERMS==3) ldsm2t(bl[nt], uBl + brow + nt*16);
        }
#pragma unroll
        for(int mt=0;mt<4;mt++){
            unsigned ah[4], al[4];
            unsigned aoff = (unsigned)((wm*64 + mt*16 + l15)*AST + ks*16 + ahl)*2;
            ldsm4(ah, uAh + aoff);
            ldsm4(al, uAl + aoff);
#pragma unroll
            for(int nt=0;nt<4;nt++) mma16816(acc[mt][nt], ah, bh[nt]);
#pragma unroll
            for(int nt=0;nt<4;nt++) mma16816(acc[mt][nt], al, bh[nt]);
            if(TERMS==3){
#pragma unroll
                for(int nt=0;nt<4;nt++) mma16816(acc[mt][nt], ah, bl[nt]);
            }
        }
    }
}

// ------------------------- dense pipelined GEMM 128x128x32 -----------------
// A = g_xh/g_xl [.,K]; MODE 0: C = A@B  MODE 1: C += A@B
template<int MODE, int TERMS>
__global__ __launch_bounds__(256) void hgemm_k(int bid, size_t boff,
                                               float* Cext, int cid, int N, int K)
{
    extern __shared__ __half smp[];
    const __half* Bhg = whsel(bid)   + boff;
    const __half* Blg = whsel(bid+1) + boff;
    float* C = (cid >= 0) ? bufsel(cid) : Cext;
    const int tid = threadIdx.x;
    const int bm = blockIdx.y*128, bn = blockIdx.x*128;
    const int warp = tid>>5, lane = tid&31;
    const int wm = warp>>2, wn = warp&3, gid = lane>>2, tig = lane&3;
    const int SST = (TERMS==3) ? (2*SA+2*SB) : (2*SA+SB);
    unsigned u0 = (unsigned)__cvta_generic_to_shared(smp);

    float acc[4][4][4];
#pragma unroll
    for(int i=0;i<4;i++)
#pragma unroll
        for(int j=0;j<4;j++)
#pragma unroll
            for(int q=0;q<4;q++) acc[i][j][q]=0.f;

    auto loadSt = [&](int st, int k0){
        unsigned b = u0 + (unsigned)(st*SST)*2;
#pragma unroll
        for(int u=0;u<2;u++){
            int s = u*256+tid, r = s>>2, c8 = (s&3)*8;
            size_t g = (size_t)(bm+r)*K + k0 + c8;
            cpa16(b + (unsigned)(r*AST+c8)*2,        g_xh + g, 16);
            cpa16(b + (unsigned)(SA + r*AST+c8)*2,   g_xl + g, 16);
        }
#pragma unroll
        for(int u=0;u<2;u++){
            int s = u*256+tid, kr = s>>4, c8 = (s&15)*8;
            size_t g = (size_t)(k0+kr)*N + bn + c8;
            cpa16(b + (unsigned)(2*SA + kr*BST + c8)*2, Bhg + g, 16);
            if(TERMS==3)
                cpa16(b + (unsigned)(2*SA+SB + kr*BST + c8)*2, Blg + g, 16);
        }
        cpa_commit();
    };

    const int NT = K/BK;
    loadSt(0, 0);
    for(int kt=0; kt<NT; kt++){
        if(kt+1 < NT){ loadSt((kt+1)&1, (kt+1)*BK); cpa_wait<1>(); }
        else         { cpa_wait<0>(); }
        __syncthreads();
        unsigned b = u0 + (unsigned)((kt&1)*SST)*2;
        tile_mma16<TERMS>(b, b+SA*2, b+2*SA*2, b+(2*SA+SB)*2, acc, wm, wn, lane);
        __syncthreads();
    }
#pragma unroll
    for(int mt=0;mt<4;mt++)
#pragma unroll
        for(int h=0;h<2;h++){
            int gr = bm + wm*64 + mt*16 + gid + h*8;
#pragma unroll
            for(int nt=0;nt<4;nt++){
                int gc = bn + wn*32 + nt*8 + tig*2;
                float2* p = (float2*)(C + (size_t)gr*N + gc);
                float2 v = make_float2(acc[mt][nt][h*2], acc[mt][nt][h*2+1]);
                if(MODE==1){ float2 o = *p; v.x += o.x; v.y += o.y; }
                *p = v;
            }
        }
}

// ------------------------- embedding gather --------------------------------
__global__ void embed_k(const int* __restrict__ tok, const float* __restrict__ emb){
    int i = blockIdx.x*256 + threadIdx.x;
    int t = i >> 8;
    int d = (i & 255) * 4;
    int id = tok[t];
    *(float4*)&g_h[(size_t)t*DIM + d] = *(const float4*)&emb[(size_t)id*DIM + d];
}

// ------------------------- rmsnorm: g_h -> g_xn + hi/lo planes -------------
__global__ void rms_k(const float* __restrict__ w){
    int t = blockIdx.x, tid = threadIdx.x;
    const float* xr = g_h + (size_t)t*DIM;
    float s = 0.f;
    for(int i = tid; i < DIM; i += 256){ float v = xr[i]; s += v*v; }
#pragma unroll
    for(int o=16;o;o>>=1) s += __shfl_xor_sync(0xffffffffu, s, o);
    __shared__ float sm[8];
    if((tid&31)==0) sm[tid>>5] = s;
    __syncthreads();
    if(tid==0){
        float tot = 0.f;
#pragma unroll
        for(int i=0;i<8;i++) tot += sm[i];
        sm[0] = rsqrtf(tot/DIM + EPSF);
    }
    __syncthreads();
    float inv = sm[0];
    float* o = g_xn + (size_t)t*DIM;
    for(int i = tid; i < DIM; i += 256){
        float v = xr[i]*inv*w[i];
        o[i] = v;
        __half hh = __float2half_rn(v);
        g_xh[(size_t)t*DIM + i] = hh;
        g_xl[(size_t)t*DIM + i] = __float2half_rn(v - __half2float(hh));
    }
}

// ------------------------- RoPE (on g_qkv) ---------------------------------
__global__ void rope_k(int off, int nh, const int* __restrict__ sp){
    int i = blockIdx.x*256 + threadIdx.x;
    if(i >= TT*nh*(HD/2)) return;
    int p = i & 31;
    int rest = i >> 5;
    int hh = rest % nh;
    int t  = rest / nh;
    int pos = sp[0] + (t % SEQ);
    float inv = (float)exp(-((double)(2*p)/(double)HD) * log(10000.0));
    float ang = (float)pos * inv;
    float s, c;
    sincosf(ang, &s, &c);
    float* base = g_qkv + (size_t)t*QKVD + off + hh*HD + 2*p;
    float x1 = base[0], x2 = base[1];
    base[0] = x1*c - x2*s;
    base[1] = x1*s + x2*c;
}

// ------------------------- KV prep: fp32 qkv -> half planes ----------------
__global__ void kprep_k(){
    int i = blockIdx.x*256 + threadIdx.x;
    if(i >= NBATCH*NKV*(HD/4)*SEQ) return;
    int s  = i & (SEQ-1);
    int r  = i >> 11;
    int d4 = r & 15;
    int bk = r >> 4;
    int b = bk >> 2, kvh = bk & 3;
    float4 v = *(const float4*)(g_qkv + (size_t)(b*SEQ + s)*QKVD + 1024 + kvh*HD + d4*4);
    float vv[4] = {v.x, v.y, v.z, v.w};
#pragma unroll
    for(int c=0;c<4;c++){
        size_t d = ((size_t)bk*HD + d4*4 + c)*SEQ + s;
        __half hh = __float2half_rn(vv[c]);
        g_kth[d] = hh;
        g_ktl[d] = __float2half_rn(vv[c] - __half2float(hh));
    }
}
__global__ void vprep_k(){
    int i = blockIdx.x*256 + threadIdx.x;
    if(i >= NBATCH*NKV*SEQ*(HD/4)) return;
    int d4 = i & 15;
    int rs = i >> 4;
    int s  = rs & (SEQ-1);
    int bk = rs >> 11;
    int b = bk >> 2, kvh = bk & 3;
    float4 v = *(const float4*)(g_qkv + (size_t)(b*SEQ + s)*QKVD + 1280 + kvh*HD + d4*4);
    size_t d = (size_t)rs*HD + d4*4;
    unsigned h01, l01, h23, l23;
    split2u(v.x, v.y, h01, l01);
    split2u(v.z, v.w, h23, l23);
    *(unsigned*)&g_vh[d  ] = h01; *(unsigned*)&g_vh[d+2] = h23;
    *(unsigned*)&g_vl[d  ] = l01; *(unsigned*)&g_vl[d+2] = l23;
}

// ------------------------- tensor-core flash attention ---------------------
#define FQ  (128*72)
#define FKV (64*72)
#define FSMEM ((2*FQ + 4*FKV)*2)
__global__ __launch_bounds__(256) void fattn_k(){
    extern __shared__ __half fsm[];
    __half* sQh = fsm;
    __half* sQl = fsm + FQ;
    __half* sKh = fsm + 2*FQ;
    __half* sKl = fsm + 2*FQ + FKV;
    __half* sVh = fsm + 2*FQ + 2*FKV;
    __half* sVl = fsm + 2*FQ + 3*FKV;
    const int qt = blockIdx.x, h = blockIdx.y, b = blockIdx.z;
    const int kvh = h >> 2;
    const int tid = threadIdx.x, wid = tid>>5, lane = tid&31;
    const int gid = lane>>2, tig = lane&3, l15 = lane&15, ahl = (lane>>4)<<3;
    unsigned uQh = (unsigned)__cvta_generic_to_shared(sQh);
    unsigned uQl = (unsigned)__cvta_generic_to_shared(sQl);
    unsigned uKh = (unsigned)__cvta_generic_to_shared(sKh);
    unsigned uKl = (unsigned)__cvta_generic_to_shared(sKl);
    unsigned uVh = (unsigned)__cvta_generic_to_shared(sVh);
    unsigned uVl = (unsigned)__cvta_generic_to_shared(sVl);

#pragma unroll
    for(int u=0;u<8;u++){
        int s = u*256 + tid;
        int r = s>>4, c4 = (s&15)*4;
        float4 v = *(const float4*)(g_qkv + (size_t)(b*SEQ + qt*128 + r)*QKVD + h*HD + c4);
        v.x*=0.125f; v.y*=0.125f; v.z*=0.125f; v.w*=0.125f;
        unsigned h01,l01,h23,l23;
        split2u(v.x,v.y,h01,l01); split2u(v.z,v.w,h23,l23);
        *(unsigned*)&sQh[r*72+c4] = h01; *(unsigned*)&sQh[r*72+c4+2] = h23;
        *(unsigned*)&sQl[r*72+c4] = l01; *(unsigned*)&sQl[r*72+c4+2] = l23;
    }
    __syncthreads();
    unsigned qh[4][4], ql[4][4];
#pragma unroll
    for(int ks=0;ks<4;ks++){
        unsigned aoff = (unsigned)((wid*16 + l15)*72 + ks*16 + ahl)*2;
        ldsm4(qh[ks], uQh + aoff);
        ldsm4(ql[ks], uQl + aoff);
    }

    float o[8][4];
#pragma unroll
    for(int j=0;j<8;j++){ o[j][0]=0.f; o[j][1]=0.f; o[j][2]=0.f; o[j][3]=0.f; }
    float m0=-1e30f, m1=-1e30f, l0=0.f, l1=0.f;

    const int jmax = 2*qt + 1;
    for(int jt=0;jt<=jmax;jt++){
        __syncthreads();
#pragma unroll
        for(int u=0;u<2;u++){
            int s = u*256 + tid;
            int r = s>>3, c8 = (s&7)*8;
            size_t kg = ((size_t)(b*NKV+kvh)*HD + r)*SEQ + jt*64 + c8;
            *(uint4*)&sKh[r*72+c8] = *(const uint4*)(g_kth + kg);
            *(uint4*)&sKl[r*72+c8] = *(const uint4*)(g_ktl + kg);
            size_t vg = ((size_t)(b*NKV+kvh)*SEQ + jt*64 + r)*HD + c8;
            *(uint4*)&sVh[r*72+c8] = *(const uint4*)(g_vh + vg);
            *(uint4*)&sVl[r*72+c8] = *(const uint4*)(g_vl + vg);
        }
        __syncthreads();

        float sc[8][4];
#pragma unroll
        for(int j=0;j<8;j++){ sc[j][0]=0.f; sc[j][1]=0.f; sc[j][2]=0.f; sc[j][3]=0.f; }
#pragma unroll
        for(int j=0;j<8;j++){
#pragma unroll
            for(int ks=0;ks<4;ks++){
                unsigned kbh[2], kbl[2];
                unsigned boff = (unsigned)((ks*16 + l15)*72 + j*8)*2;
                ldsm2t(kbh, uKh + boff);
                ldsm2t(kbl, uKl + boff);
                mma16816(sc[j], qh[ks], kbh);
                mma16816(sc[j], ql[ks], kbh);
                mma16816(sc[j], qh[ks], kbl);
            }
        }
        if(jt >= 2*qt){
            int q0 = qt*128 + wid*16 + gid;
#pragma unroll
            for(int j=0;j<8;j++){
                int c = jt*64 + j*8 + tig*2;
                if(c   > q0  ) sc[j][0] = -1e30f;
                if(c+1 > q0  ) sc[j][1] = -1e30f;
                if(c   > q0+8) sc[j][2] = -1e30f;
                if(c+1 > q0+8) sc[j][3] = -1e30f;
            }
        }
        float mv0=-1e30f, mv1=-1e30f;
#pragma unroll
        for(int j=0;j<8;j++){
            mv0 = fmaxf(mv0, fmaxf(sc[j][0], sc[j][1]));
            mv1 = fmaxf(mv1, fmaxf(sc[j][2], sc[j][3]));
        }
        mv0 = fmaxf(mv0, __shfl_xor_sync(0xffffffffu, mv0, 1));
        mv0 = fmaxf(mv0, __shfl_xor_sync(0xffffffffu, mv0, 2));
        mv1 = fmaxf(mv1, __shfl_xor_sync(0xffffffffu, mv1, 1));
        mv1 = fmaxf(mv1, __shfl_xor_sync(0xffffffffu, mv1, 2));
        float mn0 = fmaxf(m0, mv0), mn1 = fmaxf(m1, mv1);
        float f0 = __expf(m0 - mn0), f1 = __expf(m1 - mn1);
        float rs0 = 0.f, rs1 = 0.f;
#pragma unroll
        for(int j=0;j<8;j++){
            sc[j][0] = __expf(sc[j][0]-mn0); rs0 += sc[j][0];
            sc[j][1] = __expf(sc[j][1]-mn0); rs0 += sc[j][1];
            sc[j][2] = __expf(sc[j][2]-mn1); rs1 += sc[j][2];
            sc[j][3] = __expf(sc[j][3]-mn1); rs1 += sc[j][3];
        }
        rs0 += __shfl_xor_sync(0xffffffffu, rs0, 1);
        rs0 += __shfl_xor_sync(0xffffffffu, rs0, 2);
        rs1 += __shfl_xor_sync(0xffffffffu, rs1, 1);
        rs1 += __shfl_xor_sync(0xffffffffu, rs1, 2);
        l0 = l0*f0 + rs0;  l1 = l1*f1 + rs1;
        m0 = mn0;  m1 = mn1;
#pragma unroll
        for(int j=0;j<8;j++){
            o[j][0]*=f0; o[j][1]*=f0; o[j][2]*=f1; o[j][3]*=f1;
        }
        unsigned ph[4][4], pl[4][4];
#pragma unroll
        for(int ks=0;ks<4;ks++){
            split2u(sc[2*ks  ][0], sc[2*ks  ][1], ph[ks][0], pl[ks][0]);
            split2u(sc[2*ks  ][2], sc[2*ks  ][3], ph[ks][1], pl[ks][1]);
            split2u(sc[2*ks+1][0], sc[2*ks+1][1], ph[ks][2], pl[ks][2]);
            split2u(sc[2*ks+1][2], sc[2*ks+1][3], ph[ks][3], pl[ks][3]);
        }
#pragma unroll
        for(int j=0;j<8;j++){
#pragma unroll
            for(int ks=0;ks<4;ks++){
                unsigned vbh[2], vbl[2];
                unsigned boff = (unsigned)((ks*16 + l15)*72 + j*8)*2;
                ldsm2t(vbh, uVh + boff);
                ldsm2t(vbl, uVl + boff);
                mma16816(o[j], ph[ks], vbh);
                mma16816(o[j], pl[ks], vbh);
                mma16816(o[j], ph[ks], vbl);
            }
        }
    }
    float i0 = 1.f/l0, i1 = 1.f/l1;
    size_t t0 = (size_t)(b*SEQ + qt*128 + wid*16 + gid);
#pragma unroll
    for(int j=0;j<8;j++){
        int col = h*HD + j*8 + tig*2;
        unsigned hh, ll;
        split2u(o[j][0]*i0, o[j][1]*i0, hh, ll);
        *(unsigned*)&g_xh[t0*DIM + col] = hh;
        *(unsigned*)&g_xl[t0*DIM + col] = ll;
        split2u(o[j][2]*i1, o[j][3]*i1, hh, ll);
        *(unsigned*)&g_xh[(t0+8)*DIM + col] = hh;
        *(unsigned*)&g_xl[(t0+8)*DIM + col] = ll;
    }
}

// ------------------------- MoE routing -------------------------------------
__global__ void zero_k(){
    int i = threadIdx.x;
    if(i < NE){ g_cnt[i]=0; g_scnt[i]=0; }
}

__global__ void route_k(const float* __restrict__ gw){
    int warp = threadIdx.x>>5, lane = threadIdx.x&31;
    int t = blockIdx.x*8 + warp;
    float acc[NE];
#pragma unroll
    for(int e=0;e<NE;e++) acc[e]=0.f;
    const float* xr = g_xn + (size_t)t*DIM;
    for(int i=lane;i<DIM;i+=32){
        float xv = xr[i];
        const float* g = gw + (size_t)i*NE;
#pragma unroll
        for(int e=0;e<NE;e++) acc[e] += xv*g[e];
    }
#pragma unroll
    for(int e=0;e<NE;e++)
#pragma unroll
        for(int o=16;o;o>>=1) acc[e] += __shfl_xor_sync(0xffffffffu, acc[e], o);
    if(lane==0){
        float mx = acc[0];
#pragma unroll
        for(int e=1;e<NE;e++) mx = fmaxf(mx, acc[e]);
        float p[NE];
#pragma unroll
        for(int e=0;e<NE;e++) p[e] = __expf(acc[e]-mx);
        int e0=0;
#pragma unroll
        for(int e=1;e<NE;e++) if(p[e] > p[e0]) e0=e;
        int e1 = (e0==0)?1:0;
#pragma unroll
        for(int e=0;e<NE;e++) if(e!=e0 && p[e] > p[e1]) e1=e;
        float w0=p[e0], w1=p[e1], ws=w0+w1;
        g_tope[t*2]=e0; g_tope[t*2+1]=e1;
        g_topw[t*2]=w0/ws; g_topw[t*2+1]=w1/ws;
        atomicAdd(&g_cnt[e0],1); atomicAdd(&g_cnt[e1],1);
    }
}

__global__ void build_k(){
    if(threadIdx.x || blockIdx.x) return;
    int s=0, nt=0;
    for(int e=0;e<NE;e++){
        g_seg[e]=s;
        int c = g_cnt[e];
        int tiles = (c+127)>>7;
        for(int t2=0;t2<tiles;t2++){
            g_te[nt]=e; g_tp[nt]=s+t2*128;
            int v = c - t2*128;
            g_tv[nt] = v>128 ? 128 : v;
            nt++;
        }
        s += c;
    }
    for(; nt<MAXT; nt++) g_tv[nt]=0;
}

__global__ void scatter_k(){
    int t = blockIdx.x*256 + threadIdx.x;
    if(t >= TT) return;
#pragma unroll
    for(int j=0;j<2;j++){
        int e = g_tope[t*2+j];
        int pos = g_seg[e] + atomicAdd(&g_scnt[e],1);
        g_perm[pos]=t; g_pwgt[pos]=g_topw[t*2+j];
    }
}

// ------------------------- gathered pipelined GEMM: x @ w1/w3 --------------
template<int TERMS>
__global__ __launch_bounds__(256) void tmoe13_k(int bid, size_t lbase, int oid){
    extern __shared__ __half smp[];
    int tile = blockIdx.y;
    int valid = g_tv[tile];
    if(valid==0) return;
    int e = g_te[tile], p0 = g_tp[tile];
    size_t boff = lbase + (size_t)e*DIM*HID;
    const __half* Bhg = whsel(bid)   + boff;
    const __half* Blg = whsel(bid+1) + boff;
    float* Cout = bufsel(oid);
    __shared__ int rowtok[128];
    const int tid = threadIdx.x;
    const int bn = blockIdx.x*128;
    if(tid < 128) rowtok[tid] = (tid < valid) ? g_perm[p0+tid] : -1;
    __syncthreads();
    const int warp = tid>>5, lane = tid&31;
    const int wm = warp>>2, wn = warp&3, gid = lane>>2, tig = lane&3;
    const int SST = (TERMS==3) ? (2*SA+2*SB) : (2*SA+SB);
    unsigned u0 = (unsigned)__cvta_generic_to_shared(smp);
    float acc[4][4][4];
#pragma unroll
    for(int i=0;i<4;i++)
#pragma unroll
        for(int j=0;j<4;j++)
#pragma unroll
            for(int q=0;q<4;q++) acc[i][j][q]=0.f;

    auto loadSt = [&](int st, int k0){
        unsigned b = u0 + (unsigned)(st*SST)*2;
#pragma unroll
        for(int u=0;u<2;u++){
            int s = u*256+tid, r = s>>2, c8 = (s&3)*8;
            int tk = rowtok[r];
            unsigned pr = (tk>=0) ? 16u : 0u;
            size_t g = (size_t)(tk>=0 ? tk : 0)*DIM + k0 + c8;
            cpa16(b + (unsigned)(r*AST+c8)*2,      g_xh + g, pr);
            cpa16(b + (unsigned)(SA + r*AST+c8)*2, g_xl + g, pr);
        }
#pragma unroll
        for(int u=0;u<2;u++){
            int s = u*256+tid, kr = s>>4, c8 = (s&15)*8;
            size_t g = (size_t)(k0+kr)*HID + bn + c8;
            cpa16(b + (unsigned)(2*SA + kr*BST + c8)*2,    Bhg + g, 16);
            if(TERMS==3)
                cpa16(b + (unsigned)(2*SA+SB + kr*BST + c8)*2, Blg + g, 16);
        }
        cpa_commit();
    };

    const int NT = DIM/BK;
    loadSt(0, 0);
    for(int kt=0; kt<NT; kt++){
        if(kt+1 < NT){ loadSt((kt+1)&1, (kt+1)*BK); cpa_wait<1>(); }
        else         { cpa_wait<0>(); }
        __syncthreads();
        unsigned b = u0 + (unsigned)((kt&1)*SST)*2;
        tile_mma16<TERMS>(b, b+SA*2, b+2*SA*2, b+(2*SA+SB)*2, acc, wm, wn, lane);
        __syncthreads();
    }
#pragma unroll
    for(int mt=0;mt<4;mt++)
#pragma unroll
        for(int h=0;h<2;h++){
            int lr = wm*64 + mt*16 + gid + h*8;
            if(lr >= valid) continue;
            size_t rowoff = (size_t)(p0+lr)*HID + bn;
#pragma unroll
            for(int nt=0;nt<4;nt++){
                int lc = wn*32 + nt*8 + tig*2;
                *(float2*)(Cout + rowoff + lc) =
                    make_float2(acc[mt][nt][h*2], acc[mt][nt][h*2+1]);
            }
        }
}

// ------------------------- silu(b1)*b3 -> g_xh/g_xl ------------------------
__global__ void silu_k(){
    size_t i = ((size_t)blockIdx.x*256 + threadIdx.x)*4;
    float4 a = *(float4*)&g_b1[i];
    float4 b = *(float4*)&g_b3[i];
    float rx = a.x/(1.f+__expf(-a.x))*b.x;
    float ry = a.y/(1.f+__expf(-a.y))*b.y;
    float rz = a.z/(1.f+__expf(-a.z))*b.z;
    float rw = a.w/(1.f+__expf(-a.w))*b.w;
    unsigned h01,l01,h23,l23;
    split2u(rx,ry,h01,l01); split2u(rz,rw,h23,l23);
    *(unsigned*)&g_xh[i  ] = h01; *(unsigned*)&g_xh[i+2] = h23;
    *(unsigned*)&g_xl[i  ] = l01; *(unsigned*)&g_xl[i+2] = l23;
}

// ------------------------- act @ w2, weighted scatter-add into g_h ---------
template<int TERMS>
__global__ __launch_bounds__(256) void tmoe2_k(int bid, size_t lbase){
    extern __shared__ __half smp[];
    int tile = blockIdx.y;
    int valid = g_tv[tile];
    if(valid==0) return;
    int e = g_te[tile], p0 = g_tp[tile];
    size_t boff = lbase + (size_t)e*HID*DIM;
    const __half* Bhg = whsel(bid)   + boff;
    const __half* Blg = whsel(bid+1) + boff;
    const int tid = threadIdx.x;
    const int bn = blockIdx.x*128;
    const int warp = tid>>5, lane = tid&31;
    const int wm = warp>>2, wn = warp&3, gid = lane>>2, tig = lane&3;
    const int SST = (TERMS==3) ? (2*SA+2*SB) : (2*SA+SB);
    unsigned u0 = (unsigned)__cvta_generic_to_shared(smp);
    float acc[4][4][4];
#pragma unroll
    for(int i=0;i<4;i++)
#pragma unroll
        for(int j=0;j<4;j++)
#pragma unroll
            for(int q=0;q<4;q++) acc[i][j][q]=0.f;

    auto loadSt = [&](int st, int k0){
        unsigned b = u0 + (unsigned)(st*SST)*2;
#pragma unroll
        for(int u=0;u<2;u++){
            int s = u*256+tid, r = s>>2, c8 = (s&3)*8;
            unsigned pr = (r<valid) ? 16u : 0u;
            size_t g = (size_t)(p0 + (r<valid ? r : 0))*HID + k0 + c8;
            cpa16(b + (unsigned)(r*AST+c8)*2,      g_xh + g, pr);
            cpa16(b + (unsigned)(SA + r*AST+c8)*2, g_xl + g, pr);
        }
#pragma unroll
        for(int u=0;u<2;u++){
            int s = u*256+tid, kr = s>>4, c8 = (s&15)*8;
            size_t g = (size_t)(k0+kr)*DIM + bn + c8;
            cpa16(b + (unsigned)(2*SA + kr*BST + c8)*2,    Bhg + g, 16);
            if(TERMS==3)
                cpa16(b + (unsigned)(2*SA+SB + kr*BST + c8)*2, Blg + g, 16);
        }
        cpa_commit();
    };

    const int NT = HID/BK;
    loadSt(0, 0);
    for(int kt=0; kt<NT; kt++){
        if(kt+1 < NT){ loadSt((kt+1)&1, (kt+1)*BK); cpa_wait<1>(); }
        else         { cpa_wait<0>(); }
        __syncthreads();
        unsigned b = u0 + (unsigned)((kt&1)*SST)*2;
        tile_mma16<TERMS>(b, b+SA*2, b+2*SA*2, b+(2*SA+SB)*2, acc, wm, wn, lane);
        __syncthreads();
    }
#pragma unroll
    for(int mt=0;mt<4;mt++)
#pragma unroll
        for(int h=0;h<2;h++){
            int lr = wm*64 + mt*16 + gid + h*8;
            if(lr >= valid) continue;
            int p  = p0 + lr;
            int tk = g_perm[p];
            float wf = g_pwgt[p];
            float* hrow = g_h + (size_t)tk*DIM + bn;
#pragma unroll
            for(int nt=0;nt<4;nt++){
                int lc = wn*32 + nt*8 + tig*2;
                atomicAdd(&hrow[lc  ], wf*acc[mt][nt][h*2  ]);
                atomicAdd(&hrow[lc+1], wf*acc[mt][nt][h*2+1]);
            }
        }
}

// ------------------------- host orchestration ------------------------------
extern "C" void kernel_launch(void* const* d_in, const int* in_sizes, int n_in,
                              void* d_out, int out_size)
{
    const int*   tokens    = (const int*)  d_in[0];
    const int*   sp        = (const int*)  d_in[1];
    const float* tok_emb   = (const float*)d_in[2];
    const float* attn_norm = (const float*)d_in[3];
    const float* wq        = (const float*)d_in[4];
    const float* wk        = (const float*)d_in[5];
    const float* wv        = (const float*)d_in[6];
    const float* wo        = (const float*)d_in[7];
    const float* ffn_norm  = (const float*)d_in[8];
    const float* gate      = (const float*)d_in[9];
    const float* w1        = (const float*)d_in[10];
    const float* w2        = (const float*)d_in[11];
    const float* w3        = (const float*)d_in[12];
    const float* normw     = (const float*)d_in[13];
    const float* outw      = (const float*)d_in[14];
    float* out = (float*)d_out;

    const int SM3 = (2*SA+2*SB)*2*2;   /* 75776 B */
    const int SM2 = (2*SA+SB)*2*2;     /* 58368 B */
    cudaFuncSetAttribute(hgemm_k<0,3>, cudaFuncAttributeMaxDynamicSharedMemorySize, SM3);
    cudaFuncSetAttribute(hgemm_k<1,3>, cudaFuncAttributeMaxDynamicSharedMemorySize, SM3);
    cudaFuncSetAttribute(hgemm_k<0,2>, cudaFuncAttributeMaxDynamicSharedMemorySize, SM2);
    cudaFuncSetAttribute(tmoe13_k<3>,  cudaFuncAttributeMaxDynamicSharedMemorySize, SM3);
    cudaFuncSetAttribute(tmoe13_k<2>,  cudaFuncAttributeMaxDynamicSharedMemorySize, SM2);
    cudaFuncSetAttribute(tmoe2_k<3>,   cudaFuncAttributeMaxDynamicSharedMemorySize, SM3);
    cudaFuncSetAttribute(tmoe2_k<2>,   cudaFuncAttributeMaxDynamicSharedMemorySize, SM2);
    cudaFuncSetAttribute(fattn_k,      cudaFuncAttributeMaxDynamicSharedMemorySize, FSMEM);

    // ---- weight prep (hi/lo fp16 planes) ----
    {
        int n4;
        n4 = NL*DIM*DIM/4;     cvtpack_k<<<(n4+255)/256,256>>>(wq, DIM,  0,    n4);
        n4 = NL*DIM*KVD/4;     cvtpack_k<<<(n4+255)/256,256>>>(wk, KVD,  1024, n4);
        n4 = NL*DIM*KVD/4;     cvtpack_k<<<(n4+255)/256,256>>>(wv, KVD,  1280, n4);
        n4 = NL*DIM*DIM/4;     cvt_k<<<(n4+255)/256,256>>>(wo,   6, 7,  n4);
        n4 = NL*NE*DIM*HID/4;  cvt_k<<<(n4+255)/256,256>>>(w1,   8, 9,  n4);
        n4 = NL*NE*DIM*HID/4;  cvt_k<<<(n4+255)/256,256>>>(w3,  10, 11, n4);
        n4 = NL*NE*HID*DIM/4;  cvt_k<<<(n4+255)/256,256>>>(w2,  12, 13, n4);
        n4 = DIM*VOCAB/4;      cvt_k<<<(n4+255)/256,256>>>(outw,14, 15, n4);
    }

    embed_k<<<TT*(DIM/4)/256, 256>>>(tokens, tok_emb);

    const int nkv4 = NBATCH*NKV*(HD/4)*SEQ;

    for(int l=0;l<NL;l++){
        size_t lqkv = (size_t)l*DIM*QKVD, lq = (size_t)l*DIM*DIM;
        size_t l13 = (size_t)l*NE*DIM*HID, l2 = (size_t)l*NE*HID*DIM;

        rms_k<<<TT,256>>>(attn_norm + (size_t)l*DIM);
        hgemm_k<0,3><<<dim3(QKVD/128, TT/128), 256, SM3>>>(0, lqkv, nullptr, 2, QKVD, DIM);
        rope_k<<<TT*NH*(HD/2)/256, 256>>>(0, NH, sp);
        rope_k<<<TT*NKV*(HD/2)/256, 256>>>(1024, NKV, sp);
        kprep_k<<<(nkv4+255)/256, 256>>>();
        vprep_k<<<(nkv4+255)/256, 256>>>();
        fattn_k<<<dim3(SEQ/128, NH, NBATCH), 256, FSMEM>>>();
        hgemm_k<1,3><<<dim3(DIM/128, TT/128), 256, SM3>>>(6, lq, nullptr, 0, DIM, DIM);

        rms_k<<<TT,256>>>(ffn_norm + (size_t)l*DIM);
        zero_k<<<1,32>>>();
        route_k<<<TT/8,256>>>(gate + (size_t)l*DIM*NE);
        build_k<<<1,1>>>();
        scatter_k<<<TT/256,256>>>();
        if(l == 0){
            tmoe13_k<3><<<dim3(HID/128, MAXT), 256, SM3>>>(8,  l13, 6);
            tmoe13_k<3><<<dim3(HID/128, MAXT), 256, SM3>>>(10, l13, 7);
            silu_k<<<(TT*2*HID/4)/256, 256>>>();
            tmoe2_k<3><<<dim3(DIM/128, MAXT), 256, SM3>>>(12, l2);
        } else {
            tmoe13_k<2><<<dim3(HID/128, MAXT), 256, SM2>>>(8,  l13, 6);
            tmoe13_k<2><<<dim3(HID/128, MAXT), 256, SM2>>>(10, l13, 7);
            silu_k<<<(TT*2*HID/4)/256, 256>>>();
            tmoe2_k<2><<<dim3(DIM/128, MAXT), 256, SM2>>>(12, l2);
        }
    }

    rms_k<<<TT,256>>>(normw);
    hgemm_k<0,2><<<dim3(VOCAB/128, TT/128), 256, SM2>>>(14, 0, out, -1, VOCAB, DIM);
}

// round 15
// speedup vs baseline: 1.2887x; 1.2887x over previous
#include <cuda_runtime.h>
#include <cuda_fp16.h>
#include <math.h>

#define NBATCH 2
#define SEQ 2048
#define TT (NBATCH*SEQ)      /* 4096 tokens */
#define DIM 1024
#define NH 16
#define NKV 4
#define HD 64
#define KVD (NKV*HD)         /* 256 */
#define QKVD 1536            /* 1024 q + 256 k + 256 v */
#define NE 8
#define HID 2816
#define VOCAB 32000
#define NL 2
#define EPSF 1e-6f
#define MAXT 72

// ------------------------- fp32 scratch ------------------------------------
__device__ float g_h  [TT*DIM];
__device__ float g_xn [TT*DIM];
__device__ float g_qkv[TT*QKVD];
__device__ float g_b1 [TT*2*HID];
__device__ int   g_tope[TT*2];
__device__ float g_topw[TT*2];
__device__ int   g_cnt[NE];
__device__ int   g_scnt[NE];
__device__ int   g_seg[NE];
__device__ int   g_perm[TT*2];
__device__ float g_pwgt[TT*2];
__device__ int   g_te[MAXT], g_tp[MAXT], g_tv[MAXT];

// ------------------------- activation hi/lo half planes --------------------
__device__ __half g_xh[TT*DIM], g_xl[TT*DIM];          /* token-indexed activations */
__device__ __half g_ah[TT*2*HID], g_al[TT*2*HID];      /* MoE intermediate (permuted rows) */

// ------------------------- KV half planes (K transposed per head) ----------
__device__ __half g_kth[NBATCH*NKV*HD*SEQ], g_ktl[NBATCH*NKV*HD*SEQ];
__device__ __half g_vh [NBATCH*NKV*SEQ*HD], g_vl [NBATCH*NKV*SEQ*HD];

// ------------------------- half hi/lo weight planes ------------------------
__device__ __half w_qkvh[NL*DIM*QKVD], w_qkvl[NL*DIM*QKVD];
__device__ __half w_oh[NL*DIM*DIM],   w_ol[NL*DIM*DIM];
__device__ __half w1h[NL*NE*DIM*HID], w1l[NL*NE*DIM*HID];
__device__ __half w3h[NL*NE*DIM*HID], w3l[NL*NE*DIM*HID];
__device__ __half w2h[NL*NE*HID*DIM], w2l[NL*NE*HID*DIM];
__device__ __half wouth[DIM*VOCAB],   woutl[DIM*VOCAB];

__device__ __forceinline__ float* bufsel(int id){
    switch(id){
        case 0: return g_h;
        case 1: return g_xn;
        case 2: return g_qkv;
        default: return g_b1;
    }
}
__device__ __forceinline__ __half* whsel(int id){
    switch(id){
        case 0:  return w_qkvh; case 1:  return w_qkvl;
        case 6:  return w_oh;   case 7:  return w_ol;
        case 8:  return w1h;    case 9:  return w1l;
        case 10: return w3h;    case 11: return w3l;
        case 12: return w2h;    case 13: return w2l;
        case 14: return wouth;  default: return woutl;
    }
}

// ------------------------- weight prep -------------------------------------
__global__ void cvt_k(const float* __restrict__ src, int hid, int lid, int n4){
    int i = blockIdx.x*256 + threadIdx.x;
    if(i >= n4) return;
    __half* hi = whsel(hid);
    __half* lo = whsel(lid);
    float4 v = ((const float4*)src)[i];
    __half h0=__float2half_rn(v.x), h1=__float2half_rn(v.y);
    __half h2=__float2half_rn(v.z), h3=__float2half_rn(v.w);
    __half l0=__float2half_rn(v.x-__half2float(h0));
    __half l1=__float2half_rn(v.y-__half2float(h1));
    __half l2=__float2half_rn(v.z-__half2float(h2));
    __half l3=__float2half_rn(v.w-__half2float(h3));
    ((__half2*)hi)[i*2  ] = __halves2half2(h0,h1);
    ((__half2*)hi)[i*2+1] = __halves2half2(h2,h3);
    ((__half2*)lo)[i*2  ] = __halves2half2(l0,l1);
    ((__half2*)lo)[i*2+1] = __halves2half2(l2,l3);
}

// pack wq/wk/wv columns into the combined [row][QKVD] planes
__global__ void cvtpack_k(const float* __restrict__ src, int Nsrc, int coloff, int n4){
    int i = blockIdx.x*256 + threadIdx.x;
    if(i >= n4) return;
    float4 v = ((const float4*)src)[i];
    int e = i*4;
    int row = e / Nsrc, col = e % Nsrc;
    size_t d = (size_t)row*QKVD + coloff + col;
    __half h0=__float2half_rn(v.x), h1=__float2half_rn(v.y);
    __half h2=__float2half_rn(v.z), h3=__float2half_rn(v.w);
    __half l0=__float2half_rn(v.x-__half2float(h0));
    __half l1=__float2half_rn(v.y-__half2float(h1));
    __half l2=__float2half_rn(v.z-__half2float(h2));
    __half l3=__float2half_rn(v.w-__half2float(h3));
    *(__half2*)&w_qkvh[d  ] = __halves2half2(h0,h1);
    *(__half2*)&w_qkvh[d+2] = __halves2half2(h2,h3);
    *(__half2*)&w_qkvl[d  ] = __halves2half2(l0,l1);
    *(__half2*)&w_qkvl[d+2] = __halves2half2(l2,l3);
}

// ------------------------- mma / ldmatrix / cp.async helpers ---------------
__device__ __forceinline__ void mma16816(float* c, const unsigned* a, const unsigned* b){
    asm volatile("mma.sync.aligned.m16n8k16.row.col.f32.f16.f16.f32 "
        "{%0,%1,%2,%3}, {%4,%5,%6,%7}, {%8,%9}, {%0,%1,%2,%3};"
        : "+f"(c[0]),"+f"(c[1]),"+f"(c[2]),"+f"(c[3])
        : "r"(a[0]),"r"(a[1]),"r"(a[2]),"r"(a[3]),"r"(b[0]),"r"(b[1]));
}
__device__ __forceinline__ void ldsm4(unsigned* r, unsigned addr){
    asm volatile("ldmatrix.sync.aligned.m8n8.x4.shared.b16 {%0,%1,%2,%3}, [%4];"
        : "=r"(r[0]),"=r"(r[1]),"=r"(r[2]),"=r"(r[3]) : "r"(addr));
}
__device__ __forceinline__ void ldsm2t(unsigned* r, unsigned addr){
    asm volatile("ldmatrix.sync.aligned.m8n8.x2.trans.shared.b16 {%0,%1}, [%2];"
        : "=r"(r[0]),"=r"(r[1]) : "r"(addr));
}
__device__ __forceinline__ void cpa16(unsigned dst, const void* src, unsigned sz){
    asm volatile("cp.async.cg.shared.global [%0], [%1], 16, %2;" :: "r"(dst), "l"(src), "r"(sz));
}
__device__ __forceinline__ void cpa_commit(){ asm volatile("cp.async.commit_group;"); }
template<int N>
__device__ __forceinline__ void cpa_wait(){ asm volatile("cp.async.wait_group %0;" :: "n"(N)); }

__device__ __forceinline__ void split2u(float a, float b, unsigned &hi, unsigned &lo){
    __half h0=__float2half_rn(a), h1=__float2half_rn(b);
    __half l0=__float2half_rn(a-__half2float(h0));
    __half l1=__float2half_rn(b-__half2float(h1));
    hi = (unsigned)__half_as_ushort(h0) | ((unsigned)__half_as_ushort(h1)<<16);
    lo = (unsigned)__half_as_ushort(l0) | ((unsigned)__half_as_ushort(l1)<<16);
}

#define BK 32
#define AST 40    /* A smem row stride (halfs) */
#define BST 136   /* B smem row stride (halfs) */
#define SA (128*AST)   /* 5120 halfs per A plane */
#define SB (BK*BST)    /* 4352 halfs per B plane */

// warp-tile compute over one BK tile
template<int TERMS>
__device__ __forceinline__ void tile_mma16(unsigned uAh, unsigned uAl, unsigned uBh, unsigned uBl,
                                           float acc[4][4][4], int wm, int wn, int lane){
    const int l15 = lane & 15;
    const int ahl = ((lane>>4)<<3);
#pragma unroll
    for(int ks=0;ks<2;ks++){
        unsigned bh[4][2], bl[4][2];
        unsigned brow = (unsigned)((ks*16 + l15)*BST + wn*32)*2;
#pragma unroll
        for(int nt=0;nt<4;nt++){
            ldsm2t(bh[nt], uBh + brow + nt*16);
            if(TERMS==3) ldsm2t(bl[nt], uBl + brow + nt*16);
        }
#pragma unroll
        for(int mt=0;mt<4;mt++){
            unsigned ah[4], al[4];
            unsigned aoff = (unsigned)((wm*64 + mt*16 + l15)*AST + ks*16 + ahl)*2;
            ldsm4(ah, uAh + aoff);
            ldsm4(al, uAl + aoff);
#pragma unroll
            for(int nt=0;nt<4;nt++) mma16816(acc[mt][nt], ah, bh[nt]);
#pragma unroll
            for(int nt=0;nt<4;nt++) mma16816(acc[mt][nt], al, bh[nt]);
            if(TERMS==3){
#pragma unroll
                for(int nt=0;nt<4;nt++) mma16816(acc[mt][nt], ah, bl[nt]);
            }
        }
    }
}

// ------------------------- dense pipelined GEMM 128x128x32 -----------------
// A = g_xh/g_xl [.,K]; MODE 0: C = A@B  MODE 1: C += A@B
template<int MODE, int TERMS>
__global__ __launch_bounds__(256) void hgemm_k(int bid, size_t boff,
                                               float* Cext, int cid, int N, int K)
{
    extern __shared__ __half smp[];
    const __half* Bhg = whsel(bid)   + boff;
    const __half* Blg = whsel(bid+1) + boff;
    float* C = (cid >= 0) ? bufsel(cid) : Cext;
    const int tid = threadIdx.x;
    const int bm = blockIdx.y*128, bn = blockIdx.x*128;
    const int warp = tid>>5, lane = tid&31;
    const int wm = warp>>2, wn = warp&3, gid = lane>>2, tig = lane&3;
    const int SST = (TERMS==3) ? (2*SA+2*SB) : (2*SA+SB);
    unsigned u0 = (unsigned)__cvta_generic_to_shared(smp);

    float acc[4][4][4];
#pragma unroll
    for(int i=0;i<4;i++)
#pragma unroll
        for(int j=0;j<4;j++)
#pragma unroll
            for(int q=0;q<4;q++) acc[i][j][q]=0.f;

    auto loadSt = [&](int st, int k0){
        unsigned b = u0 + (unsigned)(st*SST)*2;
#pragma unroll
        for(int u=0;u<2;u++){
            int s = u*256+tid, r = s>>2, c8 = (s&3)*8;
            size_t g = (size_t)(bm+r)*K + k0 + c8;
            cpa16(b + (unsigned)(r*AST+c8)*2,        g_xh + g, 16);
            cpa16(b + (unsigned)(SA + r*AST+c8)*2,   g_xl + g, 16);
        }
#pragma unroll
        for(int u=0;u<2;u++){
            int s = u*256+tid, kr = s>>4, c8 = (s&15)*8;
            size_t g = (size_t)(k0+kr)*N + bn + c8;
            cpa16(b + (unsigned)(2*SA + kr*BST + c8)*2, Bhg + g, 16);
            if(TERMS==3)
                cpa16(b + (unsigned)(2*SA+SB + kr*BST + c8)*2, Blg + g, 16);
        }
        cpa_commit();
    };

    const int NT = K/BK;
    loadSt(0, 0);
    for(int kt=0; kt<NT; kt++){
        if(kt+1 < NT){ loadSt((kt+1)&1, (kt+1)*BK); cpa_wait<1>(); }
        else         { cpa_wait<0>(); }
        __syncthreads();
        unsigned b = u0 + (unsigned)((kt&1)*SST)*2;
        tile_mma16<TERMS>(b, b+SA*2, b+2*SA*2, b+(2*SA+SB)*2, acc, wm, wn, lane);
        __syncthreads();
    }
#pragma unroll
    for(int mt=0;mt<4;mt++)
#pragma unroll
        for(int h=0;h<2;h++){
            int gr = bm + wm*64 + mt*16 + gid + h*8;
#pragma unroll
            for(int nt=0;nt<4;nt++){
                int gc = bn + wn*32 + nt*8 + tig*2;
                float2* p = (float2*)(C + (size_t)gr*N + gc);
                float2 v = make_float2(acc[mt][nt][h*2], acc[mt][nt][h*2+1]);
                if(MODE==1){ float2 o = *p; v.x += o.x; v.y += o.y; }
                *p = v;
            }
        }
}

// ------------------------- embedding gather --------------------------------
__global__ void embed_k(const int* __restrict__ tok, const float* __restrict__ emb){
    int i = blockIdx.x*256 + threadIdx.x;
    int t = i >> 8;
    int d = (i & 255) * 4;
    int id = tok[t];
    *(float4*)&g_h[(size_t)t*DIM + d] = *(const float4*)&emb[(size_t)id*DIM + d];
}

// ------------------------- rmsnorm: g_h -> g_xn + hi/lo planes -------------
__global__ void rms_k(const float* __restrict__ w){
    int t = blockIdx.x, tid = threadIdx.x;
    const float* xr = g_h + (size_t)t*DIM;
    float s = 0.f;
    for(int i = tid; i < DIM; i += 256){ float v = xr[i]; s += v*v; }
#pragma unroll
    for(int o=16;o;o>>=1) s += __shfl_xor_sync(0xffffffffu, s, o);
    __shared__ float sm[8];
    if((tid&31)==0) sm[tid>>5] = s;
    __syncthreads();
    if(tid==0){
        float tot = 0.f;
#pragma unroll
        for(int i=0;i<8;i++) tot += sm[i];
        sm[0] = rsqrtf(tot/DIM + EPSF);
    }
    __syncthreads();
    float inv = sm[0];
    float* o = g_xn + (size_t)t*DIM;
    for(int i = tid; i < DIM; i += 256){
        float v = xr[i]*inv*w[i];
        o[i] = v;
        __half hh = __float2half_rn(v);
        g_xh[(size_t)t*DIM + i] = hh;
        g_xl[(size_t)t*DIM + i] = __float2half_rn(v - __half2float(hh));
    }
}

// ------------------------- RoPE (on g_qkv) ---------------------------------
__global__ void rope_k(int off, int nh, const int* __restrict__ sp){
    int i = blockIdx.x*256 + threadIdx.x;
    if(i >= TT*nh*(HD/2)) return;
    int p = i & 31;
    int rest = i >> 5;
    int hh = rest % nh;
    int t  = rest / nh;
    int pos = sp[0] + (t % SEQ);
    float inv = (float)exp(-((double)(2*p)/(double)HD) * log(10000.0));
    float ang = (float)pos * inv;
    float s, c;
    sincosf(ang, &s, &c);
    float* base = g_qkv + (size_t)t*QKVD + off + hh*HD + 2*p;
    float x1 = base[0], x2 = base[1];
    base[0] = x1*c - x2*s;
    base[1] = x1*s + x2*c;
}

// ------------------------- KV prep: fp32 qkv -> half planes ----------------
__global__ void kprep_k(){
    int i = blockIdx.x*256 + threadIdx.x;
    if(i >= NBATCH*NKV*(HD/4)*SEQ) return;
    int s  = i & (SEQ-1);
    int r  = i >> 11;
    int d4 = r & 15;
    int bk = r >> 4;
    int b = bk >> 2, kvh = bk & 3;
    float4 v = *(const float4*)(g_qkv + (size_t)(b*SEQ + s)*QKVD + 1024 + kvh*HD + d4*4);
    float vv[4] = {v.x, v.y, v.z, v.w};
#pragma unroll
    for(int c=0;c<4;c++){
        size_t d = ((size_t)bk*HD + d4*4 + c)*SEQ + s;
        __half hh = __float2half_rn(vv[c]);
        g_kth[d] = hh;
        g_ktl[d] = __float2half_rn(vv[c] - __half2float(hh));
    }
}
__global__ void vprep_k(){
    int i = blockIdx.x*256 + threadIdx.x;
    if(i >= NBATCH*NKV*SEQ*(HD/4)) return;
    int d4 = i & 15;
    int rs = i >> 4;
    int s  = rs & (SEQ-1);
    int bk = rs >> 11;
    int b = bk >> 2, kvh = bk & 3;
    float4 v = *(const float4*)(g_qkv + (size_t)(b*SEQ + s)*QKVD + 1280 + kvh*HD + d4*4);
    size_t d = (size_t)rs*HD + d4*4;
    unsigned h01, l01, h23, l23;
    split2u(v.x, v.y, h01, l01);
    split2u(v.z, v.w, h23, l23);
    *(unsigned*)&g_vh[d  ] = h01; *(unsigned*)&g_vh[d+2] = h23;
    *(unsigned*)&g_vl[d  ] = l01; *(unsigned*)&g_vl[d+2] = l23;
}

// ------------------------- tensor-core flash attention ---------------------
#define FQ  (128*72)
#define FKV (64*72)
#define FSMEM ((2*FQ + 4*FKV)*2)
__global__ __launch_bounds__(256) void fattn_k(){
    extern __shared__ __half fsm[];
    __half* sQh = fsm;
    __half* sQl = fsm + FQ;
    __half* sKh = fsm + 2*FQ;
    __half* sKl = fsm + 2*FQ + FKV;
    __half* sVh = fsm + 2*FQ + 2*FKV;
    __half* sVl = fsm + 2*FQ + 3*FKV;
    const int qt = blockIdx.x, h = blockIdx.y, b = blockIdx.z;
    const int kvh = h >> 2;
    const int tid = threadIdx.x, wid = tid>>5, lane = tid&31;
    const int gid = lane>>2, tig = lane&3, l15 = lane&15, ahl = (lane>>4)<<3;
    unsigned uQh = (unsigned)__cvta_generic_to_shared(sQh);
    unsigned uQl = (unsigned)__cvta_generic_to_shared(sQl);
    unsigned uKh = (unsigned)__cvta_generic_to_shared(sKh);
    unsigned uKl = (unsigned)__cvta_generic_to_shared(sKl);
    unsigned uVh = (unsigned)__cvta_generic_to_shared(sVh);
    unsigned uVl = (unsigned)__cvta_generic_to_shared(sVl);

#pragma unroll
    for(int u=0;u<8;u++){
        int s = u*256 + tid;
        int r = s>>4, c4 = (s&15)*4;
        float4 v = *(const float4*)(g_qkv + (size_t)(b*SEQ + qt*128 + r)*QKVD + h*HD + c4);
        v.x*=0.125f; v.y*=0.125f; v.z*=0.125f; v.w*=0.125f;
        unsigned h01,l01,h23,l23;
        split2u(v.x,v.y,h01,l01); split2u(v.z,v.w,h23,l23);
        *(unsigned*)&sQh[r*72+c4] = h01; *(unsigned*)&sQh[r*72+c4+2] = h23;
        *(unsigned*)&sQl[r*72+c4] = l01; *(unsigned*)&sQl[r*72+c4+2] = l23;
    }
    __syncthreads();
    unsigned qh[4][4], ql[4][4];
#pragma unroll
    for(int ks=0;ks<4;ks++){
        unsigned aoff = (unsigned)((wid*16 + l15)*72 + ks*16 + ahl)*2;
        ldsm4(qh[ks], uQh + aoff);
        ldsm4(ql[ks], uQl + aoff);
    }

    float o[8][4];
#pragma unroll
    for(int j=0;j<8;j++){ o[j][0]=0.f; o[j][1]=0.f; o[j][2]=0.f; o[j][3]=0.f; }
    float m0=-1e30f, m1=-1e30f, l0=0.f, l1=0.f;

    const int jmax = 2*qt + 1;
    for(int jt=0;jt<=jmax;jt++){
        __syncthreads();
#pragma unroll
        for(int u=0;u<2;u++){
            int s = u*256 + tid;
            int r = s>>3, c8 = (s&7)*8;
            size_t kg = ((size_t)(b*NKV+kvh)*HD + r)*SEQ + jt*64 + c8;
            *(uint4*)&sKh[r*72+c8] = *(const uint4*)(g_kth + kg);
            *(uint4*)&sKl[r*72+c8] = *(const uint4*)(g_ktl + kg);
            size_t vg = ((size_t)(b*NKV+kvh)*SEQ + jt*64 + r)*HD + c8;
            *(uint4*)&sVh[r*72+c8] = *(const uint4*)(g_vh + vg);
            *(uint4*)&sVl[r*72+c8] = *(const uint4*)(g_vl + vg);
        }
        __syncthreads();

        float sc[8][4];
#pragma unroll
        for(int j=0;j<8;j++){ sc[j][0]=0.f; sc[j][1]=0.f; sc[j][2]=0.f; sc[j][3]=0.f; }
#pragma unroll
        for(int j=0;j<8;j++){
#pragma unroll
            for(int ks=0;ks<4;ks++){
                unsigned kbh[2], kbl[2];
                unsigned boff = (unsigned)((ks*16 + l15)*72 + j*8)*2;
                ldsm2t(kbh, uKh + boff);
                ldsm2t(kbl, uKl + boff);
                mma16816(sc[j], qh[ks], kbh);
                mma16816(sc[j], ql[ks], kbh);
                mma16816(sc[j], qh[ks], kbl);
            }
        }
        if(jt >= 2*qt){
            int q0 = qt*128 + wid*16 + gid;
#pragma unroll
            for(int j=0;j<8;j++){
                int c = jt*64 + j*8 + tig*2;
                if(c   > q0  ) sc[j][0] = -1e30f;
                if(c+1 > q0  ) sc[j][1] = -1e30f;
                if(c   > q0+8) sc[j][2] = -1e30f;
                if(c+1 > q0+8) sc[j][3] = -1e30f;
            }
        }
        float mv0=-1e30f, mv1=-1e30f;
#pragma unroll
        for(int j=0;j<8;j++){
            mv0 = fmaxf(mv0, fmaxf(sc[j][0], sc[j][1]));
            mv1 = fmaxf(mv1, fmaxf(sc[j][2], sc[j][3]));
        }
        mv0 = fmaxf(mv0, __shfl_xor_sync(0xffffffffu, mv0, 1));
        mv0 = fmaxf(mv0, __shfl_xor_sync(0xffffffffu, mv0, 2));
        mv1 = fmaxf(mv1, __shfl_xor_sync(0xffffffffu, mv1, 1));
        mv1 = fmaxf(mv1, __shfl_xor_sync(0xffffffffu, mv1, 2));
        float mn0 = fmaxf(m0, mv0), mn1 = fmaxf(m1, mv1);
        float f0 = __expf(m0 - mn0), f1 = __expf(m1 - mn1);
        float rs0 = 0.f, rs1 = 0.f;
#pragma unroll
        for(int j=0;j<8;j++){
            sc[j][0] = __expf(sc[j][0]-mn0); rs0 += sc[j][0];
            sc[j][1] = __expf(sc[j][1]-mn0); rs0 += sc[j][1];
            sc[j][2] = __expf(sc[j][2]-mn1); rs1 += sc[j][2];
            sc[j][3] = __expf(sc[j][3]-mn1); rs1 += sc[j][3];
        }
        rs0 += __shfl_xor_sync(0xffffffffu, rs0, 1);
        rs0 += __shfl_xor_sync(0xffffffffu, rs0, 2);
        rs1 += __shfl_xor_sync(0xffffffffu, rs1, 1);
        rs1 += __shfl_xor_sync(0xffffffffu, rs1, 2);
        l0 = l0*f0 + rs0;  l1 = l1*f1 + rs1;
        m0 = mn0;  m1 = mn1;
#pragma unroll
        for(int j=0;j<8;j++){
            o[j][0]*=f0; o[j][1]*=f0; o[j][2]*=f1; o[j][3]*=f1;
        }
        unsigned ph[4][4], pl[4][4];
#pragma unroll
        for(int ks=0;ks<4;ks++){
            split2u(sc[2*ks  ][0], sc[2*ks  ][1], ph[ks][0], pl[ks][0]);
            split2u(sc[2*ks  ][2], sc[2*ks  ][3], ph[ks][1], pl[ks][1]);
            split2u(sc[2*ks+1][0], sc[2*ks+1][1], ph[ks][2], pl[ks][2]);
            split2u(sc[2*ks+1][2], sc[2*ks+1][3], ph[ks][3], pl[ks][3]);
        }
#pragma unroll
        for(int j=0;j<8;j++){
#pragma unroll
            for(int ks=0;ks<4;ks++){
                unsigned vbh[2], vbl[2];
                unsigned boff = (unsigned)((ks*16 + l15)*72 + j*8)*2;
                ldsm2t(vbh, uVh + boff);
                ldsm2t(vbl, uVl + boff);
                mma16816(o[j], ph[ks], vbh);
                mma16816(o[j], pl[ks], vbh);
                mma16816(o[j], ph[ks], vbl);
            }
        }
    }
    float i0 = 1.f/l0, i1 = 1.f/l1;
    size_t t0 = (size_t)(b*SEQ + qt*128 + wid*16 + gid);
#pragma unroll
    for(int j=0;j<8;j++){
        int col = h*HD + j*8 + tig*2;
        unsigned hh, ll;
        split2u(o[j][0]*i0, o[j][1]*i0, hh, ll);
        *(unsigned*)&g_xh[t0*DIM + col] = hh;
        *(unsigned*)&g_xl[t0*DIM + col] = ll;
        split2u(o[j][2]*i1, o[j][3]*i1, hh, ll);
        *(unsigned*)&g_xh[(t0+8)*DIM + col] = hh;
        *(unsigned*)&g_xl[(t0+8)*DIM + col] = ll;
    }
}

// ------------------------- MoE routing -------------------------------------
__global__ void zero_k(){
    int i = threadIdx.x;
    if(i < NE){ g_cnt[i]=0; g_scnt[i]=0; }
}

__global__ void route_k(const float* __restrict__ gw){
    int warp = threadIdx.x>>5, lane = threadIdx.x&31;
    int t = blockIdx.x*8 + warp;
    float acc[NE];
#pragma unroll
    for(int e=0;e<NE;e++) acc[e]=0.f;
    const float* xr = g_xn + (size_t)t*DIM;
    for(int i=lane;i<DIM;i+=32){
        float xv = xr[i];
        const float* g = gw + (size_t)i*NE;
#pragma unroll
        for(int e=0;e<NE;e++) acc[e] += xv*g[e];
    }
#pragma unroll
    for(int e=0;e<NE;e++)
#pragma unroll
        for(int o=16;o;o>>=1) acc[e] += __shfl_xor_sync(0xffffffffu, acc[e], o);
    if(lane==0){
        float mx = acc[0];
#pragma unroll
        for(int e=1;e<NE;e++) mx = fmaxf(mx, acc[e]);
        float p[NE];
#pragma unroll
        for(int e=0;e<NE;e++) p[e] = __expf(acc[e]-mx);
        int e0=0;
#pragma unroll
        for(int e=1;e<NE;e++) if(p[e] > p[e0]) e0=e;
        int e1 = (e0==0)?1:0;
#pragma unroll
        for(int e=0;e<NE;e++) if(e!=e0 && p[e] > p[e1]) e1=e;
        float w0=p[e0], w1=p[e1], ws=w0+w1;
        g_tope[t*2]=e0; g_tope[t*2+1]=e1;
        g_topw[t*2]=w0/ws; g_topw[t*2+1]=w1/ws;
        atomicAdd(&g_cnt[e0],1); atomicAdd(&g_cnt[e1],1);
    }
}

__global__ void build_k(){
    if(threadIdx.x || blockIdx.x) return;
    int s=0, nt=0;
    for(int e=0;e<NE;e++){
        g_seg[e]=s;
        int c = g_cnt[e];
        int tiles = (c+127)>>7;
        for(int t2=0;t2<tiles;t2++){
            g_te[nt]=e; g_tp[nt]=s+t2*128;
            int v = c - t2*128;
            g_tv[nt] = v>128 ? 128 : v;
            nt++;
        }
        s += c;
    }
    for(; nt<MAXT; nt++) g_tv[nt]=0;
}

__global__ void scatter_k(){
    int t = blockIdx.x*256 + threadIdx.x;
    if(t >= TT) return;
#pragma unroll
    for(int j=0;j<2;j++){
        int e = g_tope[t*2+j];
        int pos = g_seg[e] + atomicAdd(&g_scnt[e],1);
        g_perm[pos]=t; g_pwgt[pos]=g_topw[t*2+j];
    }
}

// ------------------------- gathered pipelined GEMM: x @ w1 / w3 ------------
// FUSE=0: write fp32 to g_b1.  FUSE=1 (w3 pass): read g_b1, out = silu(b1)*acc,
// hi/lo-split and write g_ah/g_al (separate planes — no aliasing with g_xh/g_xl).
template<int TERMS, int FUSE>
__global__ __launch_bounds__(256) void tmoe13_k(int bid, size_t lbase){
    extern __shared__ __half smp[];
    int tile = blockIdx.y;
    int valid = g_tv[tile];
    if(valid==0) return;
    int e = g_te[tile], p0 = g_tp[tile];
    size_t boff = lbase + (size_t)e*DIM*HID;
    const __half* Bhg = whsel(bid)   + boff;
    const __half* Blg = whsel(bid+1) + boff;
    __shared__ int rowtok[128];
    const int tid = threadIdx.x;
    const int bn = blockIdx.x*128;
    if(tid < 128) rowtok[tid] = (tid < valid) ? g_perm[p0+tid] : -1;
    __syncthreads();
    const int warp = tid>>5, lane = tid&31;
    const int wm = warp>>2, wn = warp&3, gid = lane>>2, tig = lane&3;
    const int SST = (TERMS==3) ? (2*SA+2*SB) : (2*SA+SB);
    unsigned u0 = (unsigned)__cvta_generic_to_shared(smp);
    float acc[4][4][4];
#pragma unroll
    for(int i=0;i<4;i++)
#pragma unroll
        for(int j=0;j<4;j++)
#pragma unroll
            for(int q=0;q<4;q++) acc[i][j][q]=0.f;

    auto loadSt = [&](int st, int k0){
        unsigned b = u0 + (unsigned)(st*SST)*2;
#pragma unroll
        for(int u=0;u<2;u++){
            int s = u*256+tid, r = s>>2, c8 = (s&3)*8;
            int tk = rowtok[r];
            unsigned pr = (tk>=0) ? 16u : 0u;
            size_t g = (size_t)(tk>=0 ? tk : 0)*DIM + k0 + c8;
            cpa16(b + (unsigned)(r*AST+c8)*2,      g_xh + g, pr);
            cpa16(b + (unsigned)(SA + r*AST+c8)*2, g_xl + g, pr);
        }
#pragma unroll
        for(int u=0;u<2;u++){
            int s = u*256+tid, kr = s>>4, c8 = (s&15)*8;
            size_t g = (size_t)(k0+kr)*HID + bn + c8;
            cpa16(b + (unsigned)(2*SA + kr*BST + c8)*2,    Bhg + g, 16);
            if(TERMS==3)
                cpa16(b + (unsigned)(2*SA+SB + kr*BST + c8)*2, Blg + g, 16);
        }
        cpa_commit();
    };

    const int NT = DIM/BK;
    loadSt(0, 0);
    for(int kt=0; kt<NT; kt++){
        if(kt+1 < NT){ loadSt((kt+1)&1, (kt+1)*BK); cpa_wait<1>(); }
        else         { cpa_wait<0>(); }
        __syncthreads();
        unsigned b = u0 + (unsigned)((kt&1)*SST)*2;
        tile_mma16<TERMS>(b, b+SA*2, b+2*SA*2, b+(2*SA+SB)*2, acc, wm, wn, lane);
        __syncthreads();
    }
#pragma unroll
    for(int mt=0;mt<4;mt++)
#pragma unroll
        for(int h=0;h<2;h++){
            int lr = wm*64 + mt*16 + gid + h*8;
            if(lr >= valid) continue;
            size_t rowoff = (size_t)(p0+lr)*HID + bn;
#pragma unroll
            for(int nt=0;nt<4;nt++){
                int lc = wn*32 + nt*8 + tig*2;
                if(FUSE==0){
                    *(float2*)(g_b1 + rowoff + lc) =
                        make_float2(acc[mt][nt][h*2], acc[mt][nt][h*2+1]);
                } else {
                    float2 b1v = *(const float2*)(g_b1 + rowoff + lc);
                    float ra = b1v.x/(1.f+__expf(-b1v.x)) * acc[mt][nt][h*2];
                    float rb = b1v.y/(1.f+__expf(-b1v.y)) * acc[mt][nt][h*2+1];
                    unsigned hh, ll;
                    split2u(ra, rb, hh, ll);
                    *(unsigned*)&g_ah[rowoff + lc] = hh;
                    *(unsigned*)&g_al[rowoff + lc] = ll;
                }
            }
        }
}

// ------------------------- act @ w2, weighted scatter-add into g_h ---------
template<int TERMS>
__global__ __launch_bounds__(256) void tmoe2_k(int bid, size_t lbase){
    extern __shared__ __half smp[];
    int tile = blockIdx.y;
    int valid = g_tv[tile];
    if(valid==0) return;
    int e = g_te[tile], p0 = g_tp[tile];
    size_t boff = lbase + (size_t)e*HID*DIM;
    const __half* Bhg = whsel(bid)   + boff;
    const __half* Blg = whsel(bid+1) + boff;
    const int tid = threadIdx.x;
    const int bn = blockIdx.x*128;
    const int warp = tid>>5, lane = tid&31;
    const int wm = warp>>2, wn = warp&3, gid = lane>>2, tig = lane&3;
    const int SST = (TERMS==3) ? (2*SA+2*SB) : (2*SA+SB);
    unsigned u0 = (unsigned)__cvta_generic_to_shared(smp);
    float acc[4][4][4];
#pragma unroll
    for(int i=0;i<4;i++)
#pragma unroll
        for(int j=0;j<4;j++)
#pragma unroll
            for(int q=0;q<4;q++) acc[i][j][q]=0.f;

    auto loadSt = [&](int st, int k0){
        unsigned b = u0 + (unsigned)(st*SST)*2;
#pragma unroll
        for(int u=0;u<2;u++){
            int s = u*256+tid, r = s>>2, c8 = (s&3)*8;
            unsigned pr = (r<valid) ? 16u : 0u;
            size_t g = (size_t)(p0 + (r<valid ? r : 0))*HID + k0 + c8;
            cpa16(b + (unsigned)(r*AST+c8)*2,      g_ah + g, pr);
            cpa16(b + (unsigned)(SA + r*AST+c8)*2, g_al + g, pr);
        }
#pragma unroll
        for(int u=0;u<2;u++){
            int s = u*256+tid, kr = s>>4, c8 = (s&15)*8;
            size_t g = (size_t)(k0+kr)*DIM + bn + c8;
            cpa16(b + (unsigned)(2*SA + kr*BST + c8)*2,    Bhg + g, 16);
            if(TERMS==3)
                cpa16(b + (unsigned)(2*SA+SB + kr*BST + c8)*2, Blg + g, 16);
        }
        cpa_commit();
    };

    const int NT = HID/BK;
    loadSt(0, 0);
    for(int kt=0; kt<NT; kt++){
        if(kt+1 < NT){ loadSt((kt+1)&1, (kt+1)*BK); cpa_wait<1>(); }
        else         { cpa_wait<0>(); }
        __syncthreads();
        unsigned b = u0 + (unsigned)((kt&1)*SST)*2;
        tile_mma16<TERMS>(b, b+SA*2, b+2*SA*2, b+(2*SA+SB)*2, acc, wm, wn, lane);
        __syncthreads();
    }
#pragma unroll
    for(int mt=0;mt<4;mt++)
#pragma unroll
        for(int h=0;h<2;h++){
            int lr = wm*64 + mt*16 + gid + h*8;
            if(lr >= valid) continue;
            int p  = p0 + lr;
            int tk = g_perm[p];
            float wf = g_pwgt[p];
            float* hrow = g_h + (size_t)tk*DIM + bn;
#pragma unroll
            for(int nt=0;nt<4;nt++){
                int lc = wn*32 + nt*8 + tig*2;
                atomicAdd(&hrow[lc  ], wf*acc[mt][nt][h*2  ]);
                atomicAdd(&hrow[lc+1], wf*acc[mt][nt][h*2+1]);
            }
        }
}

// ------------------------- host orchestration ------------------------------
extern "C" void kernel_launch(void* const* d_in, const int* in_sizes, int n_in,
                              void* d_out, int out_size)
{
    const int*   tokens    = (const int*)  d_in[0];
    const int*   sp        = (const int*)  d_in[1];
    const float* tok_emb   = (const float*)d_in[2];
    const float* attn_norm = (const float*)d_in[3];
    const float* wq        = (const float*)d_in[4];
    const float* wk        = (const float*)d_in[5];
    const float* wv        = (const float*)d_in[6];
    const float* wo        = (const float*)d_in[7];
    const float* ffn_norm  = (const float*)d_in[8];
    const float* gate      = (const float*)d_in[9];
    const float* w1        = (const float*)d_in[10];
    const float* w2        = (const float*)d_in[11];
    const float* w3        = (const float*)d_in[12];
    const float* normw     = (const float*)d_in[13];
    const float* outw      = (const float*)d_in[14];
    float* out = (float*)d_out;

    const int SM3 = (2*SA+2*SB)*2*2;   /* 75776 B */
    const int SM2 = (2*SA+SB)*2*2;     /* 58368 B */
    cudaFuncSetAttribute(hgemm_k<0,3>,   cudaFuncAttributeMaxDynamicSharedMemorySize, SM3);
    cudaFuncSetAttribute(hgemm_k<1,3>,   cudaFuncAttributeMaxDynamicSharedMemorySize, SM3);
    cudaFuncSetAttribute(hgemm_k<0,2>,   cudaFuncAttributeMaxDynamicSharedMemorySize, SM2);
    cudaFuncSetAttribute((const void*)tmoe13_k<3,0>, cudaFuncAttributeMaxDynamicSharedMemorySize, SM3);
    cudaFuncSetAttribute((const void*)tmoe13_k<3,1>, cudaFuncAttributeMaxDynamicSharedMemorySize, SM3);
    cudaFuncSetAttribute((const void*)tmoe13_k<2,0>, cudaFuncAttributeMaxDynamicSharedMemorySize, SM2);
    cudaFuncSetAttribute((const void*)tmoe13_k<2,1>, cudaFuncAttributeMaxDynamicSharedMemorySize, SM2);
    cudaFuncSetAttribute(tmoe2_k<3>,     cudaFuncAttributeMaxDynamicSharedMemorySize, SM3);
    cudaFuncSetAttribute(tmoe2_k<2>,     cudaFuncAttributeMaxDynamicSharedMemorySize, SM2);
    cudaFuncSetAttribute(fattn_k,        cudaFuncAttributeMaxDynamicSharedMemorySize, FSMEM);

    // ---- weight prep (hi/lo fp16 planes) ----
    {
        int n4;
        n4 = NL*DIM*DIM/4;     cvtpack_k<<<(n4+255)/256,256>>>(wq, DIM,  0,    n4);
        n4 = NL*DIM*KVD/4;     cvtpack_k<<<(n4+255)/256,256>>>(wk, KVD,  1024, n4);
        n4 = NL*DIM*KVD/4;     cvtpack_k<<<(n4+255)/256,256>>>(wv, KVD,  1280, n4);
        n4 = NL*DIM*DIM/4;     cvt_k<<<(n4+255)/256,256>>>(wo,   6, 7,  n4);
        n4 = NL*NE*DIM*HID/4;  cvt_k<<<(n4+255)/256,256>>>(w1,   8, 9,  n4);
        n4 = NL*NE*DIM*HID/4;  cvt_k<<<(n4+255)/256,256>>>(w3,  10, 11, n4);
        n4 = NL*NE*HID*DIM/4;  cvt_k<<<(n4+255)/256,256>>>(w2,  12, 13, n4);
        n4 = DIM*VOCAB/4;      cvt_k<<<(n4+255)/256,256>>>(outw,14, 15, n4);
    }

    embed_k<<<TT*(DIM/4)/256, 256>>>(tokens, tok_emb);

    const int nkv4 = NBATCH*NKV*(HD/4)*SEQ;

    for(int l=0;l<NL;l++){
        size_t lqkv = (size_t)l*DIM*QKVD, lq = (size_t)l*DIM*DIM;
        size_t l13 = (size_t)l*NE*DIM*HID, l2 = (size_t)l*NE*HID*DIM;

        rms_k<<<TT,256>>>(attn_norm + (size_t)l*DIM);
        hgemm_k<0,3><<<dim3(QKVD/128, TT/128), 256, SM3>>>(0, lqkv, nullptr, 2, QKVD, DIM);
        rope_k<<<TT*NH*(HD/2)/256, 256>>>(0, NH, sp);
        rope_k<<<TT*NKV*(HD/2)/256, 256>>>(1024, NKV, sp);
        kprep_k<<<(nkv4+255)/256, 256>>>();
        vprep_k<<<(nkv4+255)/256, 256>>>();
        fattn_k<<<dim3(SEQ/128, NH, NBATCH), 256, FSMEM>>>();
        hgemm_k<1,3><<<dim3(DIM/128, TT/128), 256, SM3>>>(6, lq, nullptr, 0, DIM, DIM);

        rms_k<<<TT,256>>>(ffn_norm + (size_t)l*DIM);
        zero_k<<<1,32>>>();
        route_k<<<TT/8,256>>>(gate + (size_t)l*DIM*NE);
        build_k<<<1,1>>>();
        scatter_k<<<TT/256,256>>>();
        if(l == 0){
            tmoe13_k<3,0><<<dim3(HID/128, MAXT), 256, SM3>>>(8,  l13);
            tmoe13_k<3,1><<<dim3(HID/128, MAXT), 256, SM3>>>(10, l13);
            tmoe2_k<3><<<dim3(DIM/128, MAXT), 256, SM3>>>(12, l2);
        } else {
            tmoe13_k<2,0><<<dim3(HID/128, MAXT), 256, SM2>>>(8,  l13);
            tmoe13_k<2,1><<<dim3(HID/128, MAXT), 256, SM2>>>(10, l13);
            tmoe2_k<2><<<dim3(DIM/128, MAXT), 256, SM2>>>(12, l2);
        }
    }

    rms_k<<<TT,256>>>(normw);
    hgemm_k<0,2><<<dim3(VOCAB/128, TT/128), 256, SM2>>>(14, 0, out, -1, VOCAB, DIM);
}

// round 16
// speedup vs baseline: 1.4569x; 1.1305x over previous
#include <cuda_runtime.h>
#include <cuda_fp16.h>
#include <math.h>

#define NBATCH 2
#define SEQ 2048
#define TT (NBATCH*SEQ)      /* 4096 tokens */
#define DIM 1024
#define NH 16
#define NKV 4
#define HD 64
#define KVD (NKV*HD)         /* 256 */
#define QKVD 1536            /* 1024 q + 256 k + 256 v */
#define NE 8
#define HID 2816
#define VOCAB 32000
#define NL 2
#define EPSF 1e-6f
#define MAXT 72

// ------------------------- fp32 scratch ------------------------------------
__device__ float g_h  [TT*DIM];
__device__ float g_xn [TT*DIM];
__device__ float g_qkv[TT*QKVD];
__device__ float g_b1 [TT*2*HID];
__device__ int   g_tope[TT*2];
__device__ float g_topw[TT*2];
__device__ int   g_cnt[NE];
__device__ int   g_scnt[NE];
__device__ int   g_seg[NE];
__device__ int   g_perm[TT*2];
__device__ float g_pwgt[TT*2];
__device__ int   g_te[MAXT], g_tp[MAXT], g_tv[MAXT];

// ------------------------- activation hi/lo half planes --------------------
__device__ __half g_xh[TT*DIM], g_xl[TT*DIM];          /* token-indexed activations */
__device__ __half g_ah[TT*2*HID], g_al[TT*2*HID];      /* MoE intermediate (permuted rows) */

// ------------------------- KV half planes (K transposed per head) ----------
__device__ __half g_kth[NBATCH*NKV*HD*SEQ], g_ktl[NBATCH*NKV*HD*SEQ];
__device__ __half g_vh [NBATCH*NKV*SEQ*HD], g_vl [NBATCH*NKV*SEQ*HD];

// ------------------------- half hi/lo weight planes ------------------------
__device__ __half w_qkvh[NL*DIM*QKVD], w_qkvl[NL*DIM*QKVD];
__device__ __half w_oh[NL*DIM*DIM],   w_ol[NL*DIM*DIM];
__device__ __half w1h[NL*NE*DIM*HID], w1l[NL*NE*DIM*HID];
__device__ __half w3h[NL*NE*DIM*HID], w3l[NL*NE*DIM*HID];
__device__ __half w2h[NL*NE*HID*DIM], w2l[NL*NE*HID*DIM];
__device__ __half wouth[DIM*VOCAB];

__device__ __forceinline__ float* bufsel(int id){
    switch(id){
        case 0: return g_h;
        case 1: return g_xn;
        case 2: return g_qkv;
        default: return g_b1;
    }
}
__device__ __forceinline__ __half* whsel(int id){
    switch(id){
        case 0:  return w_qkvh; case 1:  return w_qkvl;
        case 6:  return w_oh;   case 7:  return w_ol;
        case 8:  return w1h;    case 9:  return w1l;
        case 10: return w3h;    case 11: return w3l;
        case 12: return w2h;    case 13: return w2l;
        default: return wouth;
    }
}

// ------------------------- weight prep -------------------------------------
__global__ void cvt_k(const float* __restrict__ src, int hid, int lid, int n4){
    int i = blockIdx.x*256 + threadIdx.x;
    if(i >= n4) return;
    __half* hi = whsel(hid);
    __half* lo = whsel(lid);
    float4 v = ((const float4*)src)[i];
    __half h0=__float2half_rn(v.x), h1=__float2half_rn(v.y);
    __half h2=__float2half_rn(v.z), h3=__float2half_rn(v.w);
    __half l0=__float2half_rn(v.x-__half2float(h0));
    __half l1=__float2half_rn(v.y-__half2float(h1));
    __half l2=__float2half_rn(v.z-__half2float(h2));
    __half l3=__float2half_rn(v.w-__half2float(h3));
    ((__half2*)hi)[i*2  ] = __halves2half2(h0,h1);
    ((__half2*)hi)[i*2+1] = __halves2half2(h2,h3);
    ((__half2*)lo)[i*2  ] = __halves2half2(l0,l1);
    ((__half2*)lo)[i*2+1] = __halves2half2(l2,l3);
}

// hi-plane-only conversion (logits weight; lo plane never read by 1-term GEMM)
__global__ void cvthi_k(const float* __restrict__ src, int hid, int n4){
    int i = blockIdx.x*256 + threadIdx.x;
    if(i >= n4) return;
    __half* hi = whsel(hid);
    float4 v = ((const float4*)src)[i];
    ((__half2*)hi)[i*2  ] = __halves2half2(__float2half_rn(v.x), __float2half_rn(v.y));
    ((__half2*)hi)[i*2+1] = __halves2half2(__float2half_rn(v.z), __float2half_rn(v.w));
}

// pack wq/wk/wv columns into the combined [row][QKVD] planes
__global__ void cvtpack_k(const float* __restrict__ src, int Nsrc, int coloff, int n4){
    int i = blockIdx.x*256 + threadIdx.x;
    if(i >= n4) return;
    float4 v = ((const float4*)src)[i];
    int e = i*4;
    int row = e / Nsrc, col = e % Nsrc;
    size_t d = (size_t)row*QKVD + coloff + col;
    __half h0=__float2half_rn(v.x), h1=__float2half_rn(v.y);
    __half h2=__float2half_rn(v.z), h3=__float2half_rn(v.w);
    __half l0=__float2half_rn(v.x-__half2float(h0));
    __half l1=__float2half_rn(v.y-__half2float(h1));
    __half l2=__float2half_rn(v.z-__half2float(h2));
    __half l3=__float2half_rn(v.w-__half2float(h3));
    *(__half2*)&w_qkvh[d  ] = __halves2half2(h0,h1);
    *(__half2*)&w_qkvh[d+2] = __halves2half2(h2,h3);
    *(__half2*)&w_qkvl[d  ] = __halves2half2(l0,l1);
    *(__half2*)&w_qkvl[d+2] = __halves2half2(l2,l3);
}

// ------------------------- mma / ldmatrix / cp.async helpers ---------------
__device__ __forceinline__ void mma16816(float* c, const unsigned* a, const unsigned* b){
    asm volatile("mma.sync.aligned.m16n8k16.row.col.f32.f16.f16.f32 "
        "{%0,%1,%2,%3}, {%4,%5,%6,%7}, {%8,%9}, {%0,%1,%2,%3};"
        : "+f"(c[0]),"+f"(c[1]),"+f"(c[2]),"+f"(c[3])
        : "r"(a[0]),"r"(a[1]),"r"(a[2]),"r"(a[3]),"r"(b[0]),"r"(b[1]));
}
__device__ __forceinline__ void ldsm4(unsigned* r, unsigned addr){
    asm volatile("ldmatrix.sync.aligned.m8n8.x4.shared.b16 {%0,%1,%2,%3}, [%4];"
        : "=r"(r[0]),"=r"(r[1]),"=r"(r[2]),"=r"(r[3]) : "r"(addr));
}
__device__ __forceinline__ void ldsm2t(unsigned* r, unsigned addr){
    asm volatile("ldmatrix.sync.aligned.m8n8.x2.trans.shared.b16 {%0,%1}, [%2];"
        : "=r"(r[0]),"=r"(r[1]) : "r"(addr));
}
__device__ __forceinline__ void cpa16(unsigned dst, const void* src, unsigned sz){
    asm volatile("cp.async.cg.shared.global [%0], [%1], 16, %2;" :: "r"(dst), "l"(src), "r"(sz));
}
__device__ __forceinline__ void cpa_commit(){ asm volatile("cp.async.commit_group;"); }
template<int N>
__device__ __forceinline__ void cpa_wait(){ asm volatile("cp.async.wait_group %0;" :: "n"(N)); }

__device__ __forceinline__ void split2u(float a, float b, unsigned &hi, unsigned &lo){
    __half h0=__float2half_rn(a), h1=__float2half_rn(b);
    __half l0=__float2half_rn(a-__half2float(h0));
    __half l1=__float2half_rn(b-__half2float(h1));
    hi = (unsigned)__half_as_ushort(h0) | ((unsigned)__half_as_ushort(h1)<<16);
    lo = (unsigned)__half_as_ushort(l0) | ((unsigned)__half_as_ushort(l1)<<16);
}

#define BK 32
#define AST 40    /* A smem row stride (halfs) */
#define BST 136   /* B smem row stride (halfs) */
#define SA (128*AST)   /* 5120 halfs per A plane */
#define SB (BK*BST)    /* 4352 halfs per B plane */

// warp-tile compute over one BK tile. TERMS: 1=ah*bh, 2=+al*bh, 3=+ah*bl
template<int TERMS>
__device__ __forceinline__ void tile_mma16(unsigned uAh, unsigned uAl, unsigned uBh, unsigned uBl,
                                           float acc[4][4][4], int wm, int wn, int lane){
    const int l15 = lane & 15;
    const int ahl = ((lane>>4)<<3);
#pragma unroll
    for(int ks=0;ks<2;ks++){
        unsigned bh[4][2], bl[4][2];
        unsigned brow = (unsigned)((ks*16 + l15)*BST + wn*32)*2;
#pragma unroll
        for(int nt=0;nt<4;nt++){
            ldsm2t(bh[nt], uBh + brow + nt*16);
            if(TERMS==3) ldsm2t(bl[nt], uBl + brow + nt*16);
        }
#pragma unroll
        for(int mt=0;mt<4;mt++){
            unsigned ah[4], al[4];
            unsigned aoff = (unsigned)((wm*64 + mt*16 + l15)*AST + ks*16 + ahl)*2;
            ldsm4(ah, uAh + aoff);
            if(TERMS>=2) ldsm4(al, uAl + aoff);
#pragma unroll
            for(int nt=0;nt<4;nt++) mma16816(acc[mt][nt], ah, bh[nt]);
            if(TERMS>=2){
#pragma unroll
                for(int nt=0;nt<4;nt++) mma16816(acc[mt][nt], al, bh[nt]);
            }
            if(TERMS==3){
#pragma unroll
                for(int nt=0;nt<4;nt++) mma16816(acc[mt][nt], ah, bl[nt]);
            }
        }
    }
}

// ------------------------- dense pipelined GEMM 128x128x32 -----------------
// A = g_xh/g_xl [.,K]; MODE 0: C = A@B  MODE 1: C += A@B
template<int MODE, int TERMS>
__global__ __launch_bounds__(256) void hgemm_k(int bid, size_t boff,
                                               float* Cext, int cid, int N, int K)
{
    extern __shared__ __half smp[];
    const __half* Bhg = whsel(bid)   + boff;
    const __half* Blg = whsel(bid+1) + boff;
    float* C = (cid >= 0) ? bufsel(cid) : Cext;
    const int tid = threadIdx.x;
    const int bm = blockIdx.y*128, bn = blockIdx.x*128;
    const int warp = tid>>5, lane = tid&31;
    const int wm = warp>>2, wn = warp&3, gid = lane>>2, tig = lane&3;
    const int SST = (TERMS==3) ? (2*SA+2*SB) : (TERMS==2) ? (2*SA+SB) : (SA+SB);
    const int AL  = (TERMS>=2) ? SA : 0;       /* Al plane offset (aliases Ah when unused) */
    const int BH  = (TERMS>=2) ? 2*SA : SA;    /* Bh plane offset */
    unsigned u0 = (unsigned)__cvta_generic_to_shared(smp);

    float acc[4][4][4];
#pragma unroll
    for(int i=0;i<4;i++)
#pragma unroll
        for(int j=0;j<4;j++)
#pragma unroll
            for(int q=0;q<4;q++) acc[i][j][q]=0.f;

    auto loadSt = [&](int st, int k0){
        unsigned b = u0 + (unsigned)(st*SST)*2;
#pragma unroll
        for(int u=0;u<2;u++){
            int s = u*256+tid, r = s>>2, c8 = (s&3)*8;
            size_t g = (size_t)(bm+r)*K + k0 + c8;
            cpa16(b + (unsigned)(r*AST+c8)*2,        g_xh + g, 16);
            if(TERMS>=2)
                cpa16(b + (unsigned)(AL + r*AST+c8)*2, g_xl + g, 16);
        }
#pragma unroll
        for(int u=0;u<2;u++){
            int s = u*256+tid, kr = s>>4, c8 = (s&15)*8;
            size_t g = (size_t)(k0+kr)*N + bn + c8;
            cpa16(b + (unsigned)(BH + kr*BST + c8)*2, Bhg + g, 16);
            if(TERMS==3)
                cpa16(b + (unsigned)(BH+SB + kr*BST + c8)*2, Blg + g, 16);
        }
        cpa_commit();
    };

    const int NT = K/BK;
    loadSt(0, 0);
    for(int kt=0; kt<NT; kt++){
        if(kt+1 < NT){ loadSt((kt+1)&1, (kt+1)*BK); cpa_wait<1>(); }
        else         { cpa_wait<0>(); }
        __syncthreads();
        unsigned b = u0 + (unsigned)((kt&1)*SST)*2;
        tile_mma16<TERMS>(b, b+AL*2, b+BH*2, b+(BH+SB)*2, acc, wm, wn, lane);
        __syncthreads();
    }
#pragma unroll
    for(int mt=0;mt<4;mt++)
#pragma unroll
        for(int h=0;h<2;h++){
            int gr = bm + wm*64 + mt*16 + gid + h*8;
#pragma unroll
            for(int nt=0;nt<4;nt++){
                int gc = bn + wn*32 + nt*8 + tig*2;
                float2* p = (float2*)(C + (size_t)gr*N + gc);
                float2 v = make_float2(acc[mt][nt][h*2], acc[mt][nt][h*2+1]);
                if(MODE==1){ float2 o = *p; v.x += o.x; v.y += o.y; }
                *p = v;
            }
        }
}

// ------------------------- embedding gather --------------------------------
__global__ void embed_k(const int* __restrict__ tok, const float* __restrict__ emb){
    int i = blockIdx.x*256 + threadIdx.x;
    int t = i >> 8;
    int d = (i & 255) * 4;
    int id = tok[t];
    *(float4*)&g_h[(size_t)t*DIM + d] = *(const float4*)&emb[(size_t)id*DIM + d];
}

// ------------------------- rmsnorm: g_h -> g_xn + hi/lo planes -------------
__global__ void rms_k(const float* __restrict__ w){
    int t = blockIdx.x, tid = threadIdx.x;
    const float* xr = g_h + (size_t)t*DIM;
    float s = 0.f;
    for(int i = tid; i < DIM; i += 256){ float v = xr[i]; s += v*v; }
#pragma unroll
    for(int o=16;o;o>>=1) s += __shfl_xor_sync(0xffffffffu, s, o);
    __shared__ float sm[8];
    if((tid&31)==0) sm[tid>>5] = s;
    __syncthreads();
    if(tid==0){
        float tot = 0.f;
#pragma unroll
        for(int i=0;i<8;i++) tot += sm[i];
        sm[0] = rsqrtf(tot/DIM + EPSF);
    }
    __syncthreads();
    float inv = sm[0];
    float* o = g_xn + (size_t)t*DIM;
    for(int i = tid; i < DIM; i += 256){
        float v = xr[i]*inv*w[i];
        o[i] = v;
        __half hh = __float2half_rn(v);
        g_xh[(size_t)t*DIM + i] = hh;
        g_xl[(size_t)t*DIM + i] = __float2half_rn(v - __half2float(hh));
    }
}

// ------------------------- RoPE (on g_qkv) ---------------------------------
__global__ void rope_k(int off, int nh, const int* __restrict__ sp){
    int i = blockIdx.x*256 + threadIdx.x;
    if(i >= TT*nh*(HD/2)) return;
    int p = i & 31;
    int rest = i >> 5;
    int hh = rest % nh;
    int t  = rest / nh;
    int pos = sp[0] + (t % SEQ);
    float inv = (float)exp(-((double)(2*p)/(double)HD) * log(10000.0));
    float ang = (float)pos * inv;
    float s, c;
    sincosf(ang, &s, &c);
    float* base = g_qkv + (size_t)t*QKVD + off + hh*HD + 2*p;
    float x1 = base[0], x2 = base[1];
    base[0] = x1*c - x2*s;
    base[1] = x1*s + x2*c;
}

// ------------------------- KV prep: fp32 qkv -> half planes ----------------
__global__ void kprep_k(){
    int i = blockIdx.x*256 + threadIdx.x;
    if(i >= NBATCH*NKV*(HD/4)*SEQ) return;
    int s  = i & (SEQ-1);
    int r  = i >> 11;
    int d4 = r & 15;
    int bk = r >> 4;
    int b = bk >> 2, kvh = bk & 3;
    float4 v = *(const float4*)(g_qkv + (size_t)(b*SEQ + s)*QKVD + 1024 + kvh*HD + d4*4);
    float vv[4] = {v.x, v.y, v.z, v.w};
#pragma unroll
    for(int c=0;c<4;c++){
        size_t d = ((size_t)bk*HD + d4*4 + c)*SEQ + s;
        __half hh = __float2half_rn(vv[c]);
        g_kth[d] = hh;
        g_ktl[d] = __float2half_rn(vv[c] - __half2float(hh));
    }
}
__global__ void vprep_k(){
    int i = blockIdx.x*256 + threadIdx.x;
    if(i >= NBATCH*NKV*SEQ*(HD/4)) return;
    int d4 = i & 15;
    int rs = i >> 4;
    int s  = rs & (SEQ-1);
    int bk = rs >> 11;
    int b = bk >> 2, kvh = bk & 3;
    float4 v = *(const float4*)(g_qkv + (size_t)(b*SEQ + s)*QKVD + 1280 + kvh*HD + d4*4);
    size_t d = (size_t)rs*HD + d4*4;
    unsigned h01, l01, h23, l23;
    split2u(v.x, v.y, h01, l01);
    split2u(v.z, v.w, h23, l23);
    *(unsigned*)&g_vh[d  ] = h01; *(unsigned*)&g_vh[d+2] = h23;
    *(unsigned*)&g_vl[d  ] = l01; *(unsigned*)&g_vl[d+2] = l23;
}

// ------------------------- tensor-core flash attention ---------------------
#define FQ  (128*72)
#define FKV (64*72)
#define FSMEM ((2*FQ + 4*FKV)*2)
__global__ __launch_bounds__(256) void fattn_k(){
    extern __shared__ __half fsm[];
    __half* sQh = fsm;
    __half* sQl = fsm + FQ;
    __half* sKh = fsm + 2*FQ;
    __half* sKl = fsm + 2*FQ + FKV;
    __half* sVh = fsm + 2*FQ + 2*FKV;
    __half* sVl = fsm + 2*FQ + 3*FKV;
    const int qt = blockIdx.x, h = blockIdx.y, b = blockIdx.z;
    const int kvh = h >> 2;
    const int tid = threadIdx.x, wid = tid>>5, lane = tid&31;
    const int gid = lane>>2, tig = lane&3, l15 = lane&15, ahl = (lane>>4)<<3;
    unsigned uQh = (unsigned)__cvta_generic_to_shared(sQh);
    unsigned uQl = (unsigned)__cvta_generic_to_shared(sQl);
    unsigned uKh = (unsigned)__cvta_generic_to_shared(sKh);
    unsigned uKl = (unsigned)__cvta_generic_to_shared(sKl);
    unsigned uVh = (unsigned)__cvta_generic_to_shared(sVh);
    unsigned uVl = (unsigned)__cvta_generic_to_shared(sVl);

#pragma unroll
    for(int u=0;u<8;u++){
        int s = u*256 + tid;
        int r = s>>4, c4 = (s&15)*4;
        float4 v = *(const float4*)(g_qkv + (size_t)(b*SEQ + qt*128 + r)*QKVD + h*HD + c4);
        v.x*=0.125f; v.y*=0.125f; v.z*=0.125f; v.w*=0.125f;
        unsigned h01,l01,h23,l23;
        split2u(v.x,v.y,h01,l01); split2u(v.z,v.w,h23,l23);
        *(unsigned*)&sQh[r*72+c4] = h01; *(unsigned*)&sQh[r*72+c4+2] = h23;
        *(unsigned*)&sQl[r*72+c4] = l01; *(unsigned*)&sQl[r*72+c4+2] = l23;
    }
    __syncthreads();
    unsigned qh[4][4], ql[4][4];
#pragma unroll
    for(int ks=0;ks<4;ks++){
        unsigned aoff = (unsigned)((wid*16 + l15)*72 + ks*16 + ahl)*2;
        ldsm4(qh[ks], uQh + aoff);
        ldsm4(ql[ks], uQl + aoff);
    }

    float o[8][4];
#pragma unroll
    for(int j=0;j<8;j++){ o[j][0]=0.f; o[j][1]=0.f; o[j][2]=0.f; o[j][3]=0.f; }
    float m0=-1e30f, m1=-1e30f, l0=0.f, l1=0.f;

    const int jmax = 2*qt + 1;
    for(int jt=0;jt<=jmax;jt++){
        __syncthreads();
#pragma unroll
        for(int u=0;u<2;u++){
            int s = u*256 + tid;
            int r = s>>3, c8 = (s&7)*8;
            size_t kg = ((size_t)(b*NKV+kvh)*HD + r)*SEQ + jt*64 + c8;
            *(uint4*)&sKh[r*72+c8] = *(const uint4*)(g_kth + kg);
            *(uint4*)&sKl[r*72+c8] = *(const uint4*)(g_ktl + kg);
            size_t vg = ((size_t)(b*NKV+kvh)*SEQ + jt*64 + r)*HD + c8;
            *(uint4*)&sVh[r*72+c8] = *(const uint4*)(g_vh + vg);
            *(uint4*)&sVl[r*72+c8] = *(const uint4*)(g_vl + vg);
        }
        __syncthreads();

        float sc[8][4];
#pragma unroll
        for(int j=0;j<8;j++){ sc[j][0]=0.f; sc[j][1]=0.f; sc[j][2]=0.f; sc[j][3]=0.f; }
#pragma unroll
        for(int j=0;j<8;j++){
#pragma unroll
            for(int ks=0;ks<4;ks++){
                unsigned kbh[2], kbl[2];
                unsigned boff = (unsigned)((ks*16 + l15)*72 + j*8)*2;
                ldsm2t(kbh, uKh + boff);
                ldsm2t(kbl, uKl + boff);
                mma16816(sc[j], qh[ks], kbh);
                mma16816(sc[j], ql[ks], kbh);
                mma16816(sc[j], qh[ks], kbl);
            }
        }
        if(jt >= 2*qt){
            int q0 = qt*128 + wid*16 + gid;
#pragma unroll
            for(int j=0;j<8;j++){
                int c = jt*64 + j*8 + tig*2;
                if(c   > q0  ) sc[j][0] = -1e30f;
                if(c+1 > q0  ) sc[j][1] = -1e30f;
                if(c   > q0+8) sc[j][2] = -1e30f;
                if(c+1 > q0+8) sc[j][3] = -1e30f;
            }
        }
        float mv0=-1e30f, mv1=-1e30f;
#pragma unroll
        for(int j=0;j<8;j++){
            mv0 = fmaxf(mv0, fmaxf(sc[j][0], sc[j][1]));
            mv1 = fmaxf(mv1, fmaxf(sc[j][2], sc[j][3]));
        }
        mv0 = fmaxf(mv0, __shfl_xor_sync(0xffffffffu, mv0, 1));
        mv0 = fmaxf(mv0, __shfl_xor_sync(0xffffffffu, mv0, 2));
        mv1 = fmaxf(mv1, __shfl_xor_sync(0xffffffffu, mv1, 1));
        mv1 = fmaxf(mv1, __shfl_xor_sync(0xffffffffu, mv1, 2));
        float mn0 = fmaxf(m0, mv0), mn1 = fmaxf(m1, mv1);
        float f0 = __expf(m0 - mn0), f1 = __expf(m1 - mn1);
        float rs0 = 0.f, rs1 = 0.f;
#pragma unroll
        for(int j=0;j<8;j++){
            sc[j][0] = __expf(sc[j][0]-mn0); rs0 += sc[j][0];
            sc[j][1] = __expf(sc[j][1]-mn0); rs0 += sc[j][1];
            sc[j][2] = __expf(sc[j][2]-mn1); rs1 += sc[j][2];
            sc[j][3] = __expf(sc[j][3]-mn1); rs1 += sc[j][3];
        }
        rs0 += __shfl_xor_sync(0xffffffffu, rs0, 1);
        rs0 += __shfl_xor_sync(0xffffffffu, rs0, 2);
        rs1 += __shfl_xor_sync(0xffffffffu, rs1, 1);
        rs1 += __shfl_xor_sync(0xffffffffu, rs1, 2);
        l0 = l0*f0 + rs0;  l1 = l1*f1 + rs1;
        m0 = mn0;  m1 = mn1;
#pragma unroll
        for(int j=0;j<8;j++){
            o[j][0]*=f0; o[j][1]*=f0; o[j][2]*=f1; o[j][3]*=f1;
        }
        unsigned ph[4][4], pl[4][4];
#pragma unroll
        for(int ks=0;ks<4;ks++){
            split2u(sc[2*ks  ][0], sc[2*ks  ][1], ph[ks][0], pl[ks][0]);
            split2u(sc[2*ks  ][2], sc[2*ks  ][3], ph[ks][1], pl[ks][1]);
            split2u(sc[2*ks+1][0], sc[2*ks+1][1], ph[ks][2], pl[ks][2]);
            split2u(sc[2*ks+1][2], sc[2*ks+1][3], ph[ks][3], pl[ks][3]);
        }
#pragma unroll
        for(int j=0;j<8;j++){
#pragma unroll
            for(int ks=0;ks<4;ks++){
                unsigned vbh[2], vbl[2];
                unsigned boff = (unsigned)((ks*16 + l15)*72 + j*8)*2;
                ldsm2t(vbh, uVh + boff);
                ldsm2t(vbl, uVl + boff);
                mma16816(o[j], ph[ks], vbh);
                mma16816(o[j], pl[ks], vbh);
                mma16816(o[j], ph[ks], vbl);
            }
        }
    }
    float i0 = 1.f/l0, i1 = 1.f/l1;
    size_t t0 = (size_t)(b*SEQ + qt*128 + wid*16 + gid);
#pragma unroll
    for(int j=0;j<8;j++){
        int col = h*HD + j*8 + tig*2;
        unsigned hh, ll;
        split2u(o[j][0]*i0, o[j][1]*i0, hh, ll);
        *(unsigned*)&g_xh[t0*DIM + col] = hh;
        *(unsigned*)&g_xl[t0*DIM + col] = ll;
        split2u(o[j][2]*i1, o[j][3]*i1, hh, ll);
        *(unsigned*)&g_xh[(t0+8)*DIM + col] = hh;
        *(unsigned*)&g_xl[(t0+8)*DIM + col] = ll;
    }
}

// ------------------------- MoE routing -------------------------------------
__global__ void zero_k(){
    int i = threadIdx.x;
    if(i < NE){ g_cnt[i]=0; g_scnt[i]=0; }
}

__global__ void route_k(const float* __restrict__ gw){
    int warp = threadIdx.x>>5, lane = threadIdx.x&31;
    int t = blockIdx.x*8 + warp;
    float acc[NE];
#pragma unroll
    for(int e=0;e<NE;e++) acc[e]=0.f;
    const float* xr = g_xn + (size_t)t*DIM;
    for(int i=lane;i<DIM;i+=32){
        float xv = xr[i];
        const float* g = gw + (size_t)i*NE;
#pragma unroll
        for(int e=0;e<NE;e++) acc[e] += xv*g[e];
    }
#pragma unroll
    for(int e=0;e<NE;e++)
#pragma unroll
        for(int o=16;o;o>>=1) acc[e] += __shfl_xor_sync(0xffffffffu, acc[e], o);
    if(lane==0){
        float mx = acc[0];
#pragma unroll
        for(int e=1;e<NE;e++) mx = fmaxf(mx, acc[e]);
        float p[NE];
#pragma unroll
        for(int e=0;e<NE;e++) p[e] = __expf(acc[e]-mx);
        int e0=0;
#pragma unroll
        for(int e=1;e<NE;e++) if(p[e] > p[e0]) e0=e;
        int e1 = (e0==0)?1:0;
#pragma unroll
        for(int e=0;e<NE;e++) if(e!=e0 && p[e] > p[e1]) e1=e;
        float w0=p[e0], w1=p[e1], ws=w0+w1;
        g_tope[t*2]=e0; g_tope[t*2+1]=e1;
        g_topw[t*2]=w0/ws; g_topw[t*2+1]=w1/ws;
        atomicAdd(&g_cnt[e0],1); atomicAdd(&g_cnt[e1],1);
    }
}

__global__ void build_k(){
    if(threadIdx.x || blockIdx.x) return;
    int s=0, nt=0;
    for(int e=0;e<NE;e++){
        g_seg[e]=s;
        int c = g_cnt[e];
        int tiles = (c+127)>>7;
        for(int t2=0;t2<tiles;t2++){
            g_te[nt]=e; g_tp[nt]=s+t2*128;
            int v = c - t2*128;
            g_tv[nt] = v>128 ? 128 : v;
            nt++;
        }
        s += c;
    }
    for(; nt<MAXT; nt++) g_tv[nt]=0;
}

__global__ void scatter_k(){
    int t = blockIdx.x*256 + threadIdx.x;
    if(t >= TT) return;
#pragma unroll
    for(int j=0;j<2;j++){
        int e = g_tope[t*2+j];
        int pos = g_seg[e] + atomicAdd(&g_scnt[e],1);
        g_perm[pos]=t; g_pwgt[pos]=g_topw[t*2+j];
    }
}

// ------------------------- gathered pipelined GEMM: x @ w1 / w3 ------------
// FUSE=0: write fp32 to g_b1.  FUSE=1 (w3 pass): read g_b1, out = silu(b1)*acc,
// hi/lo-split and write g_ah/g_al (separate planes — no aliasing with g_xh/g_xl).
template<int TERMS, int FUSE>
__global__ __launch_bounds__(256) void tmoe13_k(int bid, size_t lbase){
    extern __shared__ __half smp[];
    int tile = blockIdx.y;
    int valid = g_tv[tile];
    if(valid==0) return;
    int e = g_te[tile], p0 = g_tp[tile];
    size_t boff = lbase + (size_t)e*DIM*HID;
    const __half* Bhg = whsel(bid)   + boff;
    const __half* Blg = whsel(bid+1) + boff;
    __shared__ int rowtok[128];
    const int tid = threadIdx.x;
    const int bn = blockIdx.x*128;
    if(tid < 128) rowtok[tid] = (tid < valid) ? g_perm[p0+tid] : -1;
    __syncthreads();
    const int warp = tid>>5, lane = tid&31;
    const int wm = warp>>2, wn = warp&3, gid = lane>>2, tig = lane&3;
    const int SST = (TERMS==3) ? (2*SA+2*SB) : (2*SA+SB);
    unsigned u0 = (unsigned)__cvta_generic_to_shared(smp);
    float acc[4][4][4];
#pragma unroll
    for(int i=0;i<4;i++)
#pragma unroll
        for(int j=0;j<4;j++)
#pragma unroll
            for(int q=0;q<4;q++) acc[i][j][q]=0.f;

    auto loadSt = [&](int st, int k0){
        unsigned b = u0 + (unsigned)(st*SST)*2;
#pragma unroll
        for(int u=0;u<2;u++){
            int s = u*256+tid, r = s>>2, c8 = (s&3)*8;
            int tk = rowtok[r];
            unsigned pr = (tk>=0) ? 16u : 0u;
            size_t g = (size_t)(tk>=0 ? tk : 0)*DIM + k0 + c8;
            cpa16(b + (unsigned)(r*AST+c8)*2,      g_xh + g, pr);
            cpa16(b + (unsigned)(SA + r*AST+c8)*2, g_xl + g, pr);
        }
#pragma unroll
        for(int u=0;u<2;u++){
            int s = u*256+tid, kr = s>>4, c8 = (s&15)*8;
            size_t g = (size_t)(k0+kr)*HID + bn + c8;
            cpa16(b + (unsigned)(2*SA + kr*BST + c8)*2,    Bhg + g, 16);
            if(TERMS==3)
                cpa16(b + (unsigned)(2*SA+SB + kr*BST + c8)*2, Blg + g, 16);
        }
        cpa_commit();
    };

    const int NT = DIM/BK;
    loadSt(0, 0);
    for(int kt=0; kt<NT; kt++){
        if(kt+1 < NT){ loadSt((kt+1)&1, (kt+1)*BK); cpa_wait<1>(); }
        else         { cpa_wait<0>(); }
        __syncthreads();
        unsigned b = u0 + (unsigned)((kt&1)*SST)*2;
        tile_mma16<TERMS>(b, b+SA*2, b+2*SA*2, b+(2*SA+SB)*2, acc, wm, wn, lane);
        __syncthreads();
    }
#pragma unroll
    for(int mt=0;mt<4;mt++)
#pragma unroll
        for(int h=0;h<2;h++){
            int lr = wm*64 + mt*16 + gid + h*8;
            if(lr >= valid) continue;
            size_t rowoff = (size_t)(p0+lr)*HID + bn;
#pragma unroll
            for(int nt=0;nt<4;nt++){
                int lc = wn*32 + nt*8 + tig*2;
                if(FUSE==0){
                    *(float2*)(g_b1 + rowoff + lc) =
                        make_float2(acc[mt][nt][h*2], acc[mt][nt][h*2+1]);
                } else {
                    float2 b1v = *(const float2*)(g_b1 + rowoff + lc);
                    float ra = b1v.x/(1.f+__expf(-b1v.x)) * acc[mt][nt][h*2];
                    float rb = b1v.y/(1.f+__expf(-b1v.y)) * acc[mt][nt][h*2+1];
                    unsigned hh, ll;
                    split2u(ra, rb, hh, ll);
                    *(unsigned*)&g_ah[rowoff + lc] = hh;
                    *(unsigned*)&g_al[rowoff + lc] = ll;
                }
            }
        }
}

// ------------------------- act @ w2, weighted scatter-add into g_h ---------
template<int TERMS>
__global__ __launch_bounds__(256) void tmoe2_k(int bid, size_t lbase){
    extern __shared__ __half smp[];
    int tile = blockIdx.y;
    int valid = g_tv[tile];
    if(valid==0) return;
    int e = g_te[tile], p0 = g_tp[tile];
    size_t boff = lbase + (size_t)e*HID*DIM;
    const __half* Bhg = whsel(bid)   + boff;
    const __half* Blg = whsel(bid+1) + boff;
    const int tid = threadIdx.x;
    const int bn = blockIdx.x*128;
    const int warp = tid>>5, lane = tid&31;
    const int wm = warp>>2, wn = warp&3, gid = lane>>2, tig = lane&3;
    const int SST = (TERMS==3) ? (2*SA+2*SB) : (2*SA+SB);
    unsigned u0 = (unsigned)__cvta_generic_to_shared(smp);
    float acc[4][4][4];
#pragma unroll
    for(int i=0;i<4;i++)
#pragma unroll
        for(int j=0;j<4;j++)
#pragma unroll
            for(int q=0;q<4;q++) acc[i][j][q]=0.f;

    auto loadSt = [&](int st, int k0){
        unsigned b = u0 + (unsigned)(st*SST)*2;
#pragma unroll
        for(int u=0;u<2;u++){
            int s = u*256+tid, r = s>>2, c8 = (s&3)*8;
            unsigned pr = (r<valid) ? 16u : 0u;
            size_t g = (size_t)(p0 + (r<valid ? r : 0))*HID + k0 + c8;
            cpa16(b + (unsigned)(r*AST+c8)*2,      g_ah + g, pr);
            cpa16(b + (unsigned)(SA + r*AST+c8)*2, g_al + g, pr);
        }
#pragma unroll
        for(int u=0;u<2;u++){
            int s = u*256+tid, kr = s>>4, c8 = (s&15)*8;
            size_t g = (size_t)(k0+kr)*DIM + bn + c8;
            cpa16(b + (unsigned)(2*SA + kr*BST + c8)*2,    Bhg + g, 16);
            if(TERMS==3)
                cpa16(b + (unsigned)(2*SA+SB + kr*BST + c8)*2, Blg + g, 16);
        }
        cpa_commit();
    };

    const int NT = HID/BK;
    loadSt(0, 0);
    for(int kt=0; kt<NT; kt++){
        if(kt+1 < NT){ loadSt((kt+1)&1, (kt+1)*BK); cpa_wait<1>(); }
        else         { cpa_wait<0>(); }
        __syncthreads();
        unsigned b = u0 + (unsigned)((kt&1)*SST)*2;
        tile_mma16<TERMS>(b, b+SA*2, b+2*SA*2, b+(2*SA+SB)*2, acc, wm, wn, lane);
        __syncthreads();
    }
#pragma unroll
    for(int mt=0;mt<4;mt++)
#pragma unroll
        for(int h=0;h<2;h++){
            int lr = wm*64 + mt*16 + gid + h*8;
            if(lr >= valid) continue;
            int p  = p0 + lr;
            int tk = g_perm[p];
            float wf = g_pwgt[p];
            float* hrow = g_h + (size_t)tk*DIM + bn;
#pragma unroll
            for(int nt=0;nt<4;nt++){
                int lc = wn*32 + nt*8 + tig*2;
                atomicAdd(&hrow[lc  ], wf*acc[mt][nt][h*2  ]);
                atomicAdd(&hrow[lc+1], wf*acc[mt][nt][h*2+1]);
            }
        }
}

// ------------------------- host orchestration ------------------------------
extern "C" void kernel_launch(void* const* d_in, const int* in_sizes, int n_in,
                              void* d_out, int out_size)
{
    const int*   tokens    = (const int*)  d_in[0];
    const int*   sp        = (const int*)  d_in[1];
    const float* tok_emb   = (const float*)d_in[2];
    const float* attn_norm = (const float*)d_in[3];
    const float* wq        = (const float*)d_in[4];
    const float* wk        = (const float*)d_in[5];
    const float* wv        = (const float*)d_in[6];
    const float* wo        = (const float*)d_in[7];
    const float* ffn_norm  = (const float*)d_in[8];
    const float* gate      = (const float*)d_in[9];
    const float* w1        = (const float*)d_in[10];
    const float* w2        = (const float*)d_in[11];
    const float* w3        = (const float*)d_in[12];
    const float* normw     = (const float*)d_in[13];
    const float* outw      = (const float*)d_in[14];
    float* out = (float*)d_out;

    const int SM3 = (2*SA+2*SB)*2*2;   /* 75776 B */
    const int SM2 = (2*SA+SB)*2*2;     /* 58368 B */
    const int SM1 = (SA+SB)*2*2;       /* 37888 B */
    cudaFuncSetAttribute(hgemm_k<0,3>,   cudaFuncAttributeMaxDynamicSharedMemorySize, SM3);
    cudaFuncSetAttribute(hgemm_k<1,3>,   cudaFuncAttributeMaxDynamicSharedMemorySize, SM3);
    cudaFuncSetAttribute(hgemm_k<0,1>,   cudaFuncAttributeMaxDynamicSharedMemorySize, SM1);
    cudaFuncSetAttribute((const void*)tmoe13_k<3,0>, cudaFuncAttributeMaxDynamicSharedMemorySize, SM3);
    cudaFuncSetAttribute((const void*)tmoe13_k<3,1>, cudaFuncAttributeMaxDynamicSharedMemorySize, SM3);
    cudaFuncSetAttribute((const void*)tmoe13_k<2,0>, cudaFuncAttributeMaxDynamicSharedMemorySize, SM2);
    cudaFuncSetAttribute((const void*)tmoe13_k<2,1>, cudaFuncAttributeMaxDynamicSharedMemorySize, SM2);
    cudaFuncSetAttribute(tmoe2_k<3>,     cudaFuncAttributeMaxDynamicSharedMemorySize, SM3);
    cudaFuncSetAttribute(tmoe2_k<2>,     cudaFuncAttributeMaxDynamicSharedMemorySize, SM2);
    cudaFuncSetAttribute(fattn_k,        cudaFuncAttributeMaxDynamicSharedMemorySize, FSMEM);

    // ---- weight prep (hi/lo fp16 planes; logits hi-only) ----
    {
        int n4;
        n4 = NL*DIM*DIM/4;     cvtpack_k<<<(n4+255)/256,256>>>(wq, DIM,  0,    n4);
        n4 = NL*DIM*KVD/4;     cvtpack_k<<<(n4+255)/256,256>>>(wk, KVD,  1024, n4);
        n4 = NL*DIM*KVD/4;     cvtpack_k<<<(n4+255)/256,256>>>(wv, KVD,  1280, n4);
        n4 = NL*DIM*DIM/4;     cvt_k<<<(n4+255)/256,256>>>(wo,   6, 7,  n4);
        n4 = NL*NE*DIM*HID/4;  cvt_k<<<(n4+255)/256,256>>>(w1,   8, 9,  n4);
        n4 = NL*NE*DIM*HID/4;  cvt_k<<<(n4+255)/256,256>>>(w3,  10, 11, n4);
        n4 = NL*NE*HID*DIM/4;  cvt_k<<<(n4+255)/256,256>>>(w2,  12, 13, n4);
        n4 = DIM*VOCAB/4;      cvthi_k<<<(n4+255)/256,256>>>(outw, 14, n4);
    }

    embed_k<<<TT*(DIM/4)/256, 256>>>(tokens, tok_emb);

    const int nkv4 = NBATCH*NKV*(HD/4)*SEQ;

    for(int l=0;l<NL;l++){
        size_t lqkv = (size_t)l*DIM*QKVD, lq = (size_t)l*DIM*DIM;
        size_t l13 = (size_t)l*NE*DIM*HID, l2 = (size_t)l*NE*HID*DIM;

        rms_k<<<TT,256>>>(attn_norm + (size_t)l*DIM);
        hgemm_k<0,3><<<dim3(QKVD/128, TT/128), 256, SM3>>>(0, lqkv, nullptr, 2, QKVD, DIM);
        rope_k<<<TT*NH*(HD/2)/256, 256>>>(0, NH, sp);
        rope_k<<<TT*NKV*(HD/2)/256, 256>>>(1024, NKV, sp);
        kprep_k<<<(nkv4+255)/256, 256>>>();
        vprep_k<<<(nkv4+255)/256, 256>>>();
        fattn_k<<<dim3(SEQ/128, NH, NBATCH), 256, FSMEM>>>();
        hgemm_k<1,3><<<dim3(DIM/128, TT/128), 256, SM3>>>(6, lq, nullptr, 0, DIM, DIM);

        rms_k<<<TT,256>>>(ffn_norm + (size_t)l*DIM);
        zero_k<<<1,32>>>();
        route_k<<<TT/8,256>>>(gate + (size_t)l*DIM*NE);
        build_k<<<1,1>>>();
        scatter_k<<<TT/256,256>>>();
        if(l == 0){
            tmoe13_k<3,0><<<dim3(HID/128, MAXT), 256, SM3>>>(8,  l13);
            tmoe13_k<3,1><<<dim3(HID/128, MAXT), 256, SM3>>>(10, l13);
            tmoe2_k<3><<<dim3(DIM/128, MAXT), 256, SM3>>>(12, l2);
        } else {
            tmoe13_k<2,0><<<dim3(HID/128, MAXT), 256, SM2>>>(8,  l13);
            tmoe13_k<2,1><<<dim3(HID/128, MAXT), 256, SM2>>>(10, l13);
            tmoe2_k<2><<<dim3(DIM/128, MAXT), 256, SM2>>>(12, l2);
        }
    }

    rms_k<<<TT,256>>>(normw);
    hgemm_k<0,1><<<dim3(VOCAB/128, TT/128), 256, SM1>>>(14, 0, out, -1, VOCAB, DIM);
}

// round 17
// speedup vs baseline: 1.6014x; 1.0992x over previous
#include <cuda_runtime.h>
#include <cuda_fp16.h>
#include <math.h>

#define NBATCH 2
#define SEQ 2048
#define TT (NBATCH*SEQ)      /* 4096 tokens */
#define DIM 1024
#define NH 16
#define NKV 4
#define HD 64
#define KVD (NKV*HD)         /* 256 */
#define QKVD 1536            /* 1024 q + 256 k + 256 v */
#define NE 8
#define HID 2816
#define VOCAB 32000
#define NL 2
#define EPSF 1e-6f
#define MAXT 72

// ------------------------- fp32 scratch ------------------------------------
__device__ float g_h  [TT*DIM];
__device__ float g_xn [TT*DIM];
__device__ float g_qkv[TT*QKVD];
__device__ float g_b1 [TT*2*HID];
__device__ float2 g_rt[SEQ*32];   /* rope cos/sin table [pos][p] */
__device__ int   g_tope[TT*2];
__device__ float g_topw[TT*2];
__device__ int   g_cnt[NE];
__device__ int   g_scnt[NE];
__device__ int   g_seg[NE];
__device__ int   g_perm[TT*2];
__device__ float g_pwgt[TT*2];
__device__ int   g_te[MAXT], g_tp[MAXT], g_tv[MAXT];

// ------------------------- activation hi/lo half planes --------------------
__device__ __half g_xh[TT*DIM], g_xl[TT*DIM];          /* token-indexed activations */
__device__ __half g_ah[TT*2*HID], g_al[TT*2*HID];      /* MoE intermediate (permuted rows) */

// ------------------------- KV half planes (K transposed per head) ----------
__device__ __half g_kth[NBATCH*NKV*HD*SEQ], g_ktl[NBATCH*NKV*HD*SEQ];
__device__ __half g_vh [NBATCH*NKV*SEQ*HD], g_vl [NBATCH*NKV*SEQ*HD];

// ------------------------- half hi/lo weight planes ------------------------
__device__ __half w_qkvh[NL*DIM*QKVD], w_qkvl[NL*DIM*QKVD];
__device__ __half w_oh[NL*DIM*DIM],   w_ol[NL*DIM*DIM];
__device__ __half w1h[NL*NE*DIM*HID], w1l[NL*NE*DIM*HID];
__device__ __half w3h[NL*NE*DIM*HID], w3l[NL*NE*DIM*HID];
__device__ __half w2h[NL*NE*HID*DIM], w2l[NL*NE*HID*DIM];
__device__ __half wouth[DIM*VOCAB];

__device__ __forceinline__ float* bufsel(int id){
    switch(id){
        case 0: return g_h;
        case 1: return g_xn;
        case 2: return g_qkv;
        default: return g_b1;
    }
}
__device__ __forceinline__ __half* whsel(int id){
    switch(id){
        case 0:  return w_qkvh; case 1:  return w_qkvl;
        case 6:  return w_oh;   case 7:  return w_ol;
        case 8:  return w1h;    case 9:  return w1l;
        case 10: return w3h;    case 11: return w3l;
        case 12: return w2h;    case 13: return w2l;
        default: return wouth;
    }
}

// ------------------------- weight prep -------------------------------------
__global__ void cvt_k(const float* __restrict__ src, int hid, int lid, int n4){
    int i = blockIdx.x*256 + threadIdx.x;
    if(i >= n4) return;
    __half* hi = whsel(hid);
    __half* lo = whsel(lid);
    float4 v = ((const float4*)src)[i];
    __half h0=__float2half_rn(v.x), h1=__float2half_rn(v.y);
    __half h2=__float2half_rn(v.z), h3=__float2half_rn(v.w);
    __half l0=__float2half_rn(v.x-__half2float(h0));
    __half l1=__float2half_rn(v.y-__half2float(h1));
    __half l2=__float2half_rn(v.z-__half2float(h2));
    __half l3=__float2half_rn(v.w-__half2float(h3));
    ((__half2*)hi)[i*2  ] = __halves2half2(h0,h1);
    ((__half2*)hi)[i*2+1] = __halves2half2(h2,h3);
    ((__half2*)lo)[i*2  ] = __halves2half2(l0,l1);
    ((__half2*)lo)[i*2+1] = __halves2half2(l2,l3);
}

// hi-plane-only conversion (logits weight; lo plane never read by 1-term GEMM)
__global__ void cvthi_k(const float* __restrict__ src, int hid, int n4){
    int i = blockIdx.x*256 + threadIdx.x;
    if(i >= n4) return;
    __half* hi = whsel(hid);
    float4 v = ((const float4*)src)[i];
    ((__half2*)hi)[i*2  ] = __halves2half2(__float2half_rn(v.x), __float2half_rn(v.y));
    ((__half2*)hi)[i*2+1] = __halves2half2(__float2half_rn(v.z), __float2half_rn(v.w));
}

// pack wq/wk/wv columns into the combined [row][QKVD] planes
__global__ void cvtpack_k(const float* __restrict__ src, int Nsrc, int coloff, int n4){
    int i = blockIdx.x*256 + threadIdx.x;
    if(i >= n4) return;
    float4 v = ((const float4*)src)[i];
    int e = i*4;
    int row = e / Nsrc, col = e % Nsrc;
    size_t d = (size_t)row*QKVD + coloff + col;
    __half h0=__float2half_rn(v.x), h1=__float2half_rn(v.y);
    __half h2=__float2half_rn(v.z), h3=__float2half_rn(v.w);
    __half l0=__float2half_rn(v.x-__half2float(h0));
    __half l1=__float2half_rn(v.y-__half2float(h1));
    __half l2=__float2half_rn(v.z-__half2float(h2));
    __half l3=__float2half_rn(v.w-__half2float(h3));
    *(__half2*)&w_qkvh[d  ] = __halves2half2(h0,h1);
    *(__half2*)&w_qkvh[d+2] = __halves2half2(h2,h3);
    *(__half2*)&w_qkvl[d  ] = __halves2half2(l0,l1);
    *(__half2*)&w_qkvl[d+2] = __halves2half2(l2,l3);
}

// ------------------------- rope table (double exp once, 65K threads) -------
__global__ void ropetab_k(const int* __restrict__ sp){
    int i = blockIdx.x*256 + threadIdx.x;
    if(i >= SEQ*32) return;
    int p = i & 31, s = i >> 5;
    float inv = (float)exp(-((double)(2*p)/(double)HD) * log(10000.0));
    float ang = (float)(sp[0] + s) * inv;
    float sn, cs;
    sincosf(ang, &sn, &cs);
    g_rt[i] = make_float2(cs, sn);
}

// ------------------------- mma / ldmatrix / cp.async helpers ---------------
__device__ __forceinline__ void mma16816(float* c, const unsigned* a, const unsigned* b){
    asm volatile("mma.sync.aligned.m16n8k16.row.col.f32.f16.f16.f32 "
        "{%0,%1,%2,%3}, {%4,%5,%6,%7}, {%8,%9}, {%0,%1,%2,%3};"
        : "+f"(c[0]),"+f"(c[1]),"+f"(c[2]),"+f"(c[3])
        : "r"(a[0]),"r"(a[1]),"r"(a[2]),"r"(a[3]),"r"(b[0]),"r"(b[1]));
}
__device__ __forceinline__ void ldsm4(unsigned* r, unsigned addr){
    asm volatile("ldmatrix.sync.aligned.m8n8.x4.shared.b16 {%0,%1,%2,%3}, [%4];"
        : "=r"(r[0]),"=r"(r[1]),"=r"(r[2]),"=r"(r[3]) : "r"(addr));
}
__device__ __forceinline__ void ldsm2t(unsigned* r, unsigned addr){
    asm volatile("ldmatrix.sync.aligned.m8n8.x2.trans.shared.b16 {%0,%1}, [%2];"
        : "=r"(r[0]),"=r"(r[1]) : "r"(addr));
}
__device__ __forceinline__ void cpa16(unsigned dst, const void* src, unsigned sz){
    asm volatile("cp.async.cg.shared.global [%0], [%1], 16, %2;" :: "r"(dst), "l"(src), "r"(sz));
}
__device__ __forceinline__ void cpa_commit(){ asm volatile("cp.async.commit_group;"); }
template<int N>
__device__ __forceinline__ void cpa_wait(){ asm volatile("cp.async.wait_group %0;" :: "n"(N)); }

__device__ __forceinline__ void split2u(float a, float b, unsigned &hi, unsigned &lo){
    __half h0=__float2half_rn(a), h1=__float2half_rn(b);
    __half l0=__float2half_rn(a-__half2float(h0));
    __half l1=__float2half_rn(b-__half2float(h1));
    hi = (unsigned)__half_as_ushort(h0) | ((unsigned)__half_as_ushort(h1)<<16);
    lo = (unsigned)__half_as_ushort(l0) | ((unsigned)__half_as_ushort(l1)<<16);
}

#define BK 32
#define AST 40    /* A smem row stride (halfs) */
#define BST 136   /* B smem row stride (halfs) */
#define SA (128*AST)   /* 5120 halfs per A plane */
#define SB (BK*BST)    /* 4352 halfs per B plane */

// warp-tile compute over one BK tile. TERMS: 1=ah*bh, 2=+al*bh, 3=+ah*bl
template<int TERMS>
__device__ __forceinline__ void tile_mma16(unsigned uAh, unsigned uAl, unsigned uBh, unsigned uBl,
                                           float acc[4][4][4], int wm, int wn, int lane){
    const int l15 = lane & 15;
    const int ahl = ((lane>>4)<<3);
#pragma unroll
    for(int ks=0;ks<2;ks++){
        unsigned bh[4][2], bl[4][2];
        unsigned brow = (unsigned)((ks*16 + l15)*BST + wn*32)*2;
#pragma unroll
        for(int nt=0;nt<4;nt++){
            ldsm2t(bh[nt], uBh + brow + nt*16);
            if(TERMS==3) ldsm2t(bl[nt], uBl + brow + nt*16);
        }
#pragma unroll
        for(int mt=0;mt<4;mt++){
            unsigned ah[4], al[4];
            unsigned aoff = (unsigned)((wm*64 + mt*16 + l15)*AST + ks*16 + ahl)*2;
            ldsm4(ah, uAh + aoff);
            if(TERMS>=2) ldsm4(al, uAl + aoff);
#pragma unroll
            for(int nt=0;nt<4;nt++) mma16816(acc[mt][nt], ah, bh[nt]);
            if(TERMS>=2){
#pragma unroll
                for(int nt=0;nt<4;nt++) mma16816(acc[mt][nt], al, bh[nt]);
            }
            if(TERMS==3){
#pragma unroll
                for(int nt=0;nt<4;nt++) mma16816(acc[mt][nt], ah, bl[nt]);
            }
        }
    }
}

// ------------------------- dense pipelined GEMM 128x128x32 -----------------
// A = g_xh/g_xl [.,K]; MODE 0: C = A@B  MODE 1: C += A@B
template<int MODE, int TERMS>
__global__ __launch_bounds__(256) void hgemm_k(int bid, size_t boff,
                                               float* Cext, int cid, int N, int K)
{
    extern __shared__ __half smp[];
    const __half* Bhg = whsel(bid)   + boff;
    const __half* Blg = whsel(bid+1) + boff;
    float* C = (cid >= 0) ? bufsel(cid) : Cext;
    const int tid = threadIdx.x;
    const int bm = blockIdx.y*128, bn = blockIdx.x*128;
    const int warp = tid>>5, lane = tid&31;
    const int wm = warp>>2, wn = warp&3, gid = lane>>2, tig = lane&3;
    const int SST = (TERMS==3) ? (2*SA+2*SB) : (TERMS==2) ? (2*SA+SB) : (SA+SB);
    const int AL  = (TERMS>=2) ? SA : 0;
    const int BH  = (TERMS>=2) ? 2*SA : SA;
    unsigned u0 = (unsigned)__cvta_generic_to_shared(smp);

    float acc[4][4][4];
#pragma unroll
    for(int i=0;i<4;i++)
#pragma unroll
        for(int j=0;j<4;j++)
#pragma unroll
            for(int q=0;q<4;q++) acc[i][j][q]=0.f;

    auto loadSt = [&](int st, int k0){
        unsigned b = u0 + (unsigned)(st*SST)*2;
#pragma unroll
        for(int u=0;u<2;u++){
            int s = u*256+tid, r = s>>2, c8 = (s&3)*8;
            size_t g = (size_t)(bm+r)*K + k0 + c8;
            cpa16(b + (unsigned)(r*AST+c8)*2,        g_xh + g, 16);
            if(TERMS>=2)
                cpa16(b + (unsigned)(AL + r*AST+c8)*2, g_xl + g, 16);
        }
#pragma unroll
        for(int u=0;u<2;u++){
            int s = u*256+tid, kr = s>>4, c8 = (s&15)*8;
            size_t g = (size_t)(k0+kr)*N + bn + c8;
            cpa16(b + (unsigned)(BH + kr*BST + c8)*2, Bhg + g, 16);
            if(TERMS==3)
                cpa16(b + (unsigned)(BH+SB + kr*BST + c8)*2, Blg + g, 16);
        }
        cpa_commit();
    };

    const int NT = K/BK;
    loadSt(0, 0);
    for(int kt=0; kt<NT; kt++){
        if(kt+1 < NT){ loadSt((kt+1)&1, (kt+1)*BK); cpa_wait<1>(); }
        else         { cpa_wait<0>(); }
        __syncthreads();
        unsigned b = u0 + (unsigned)((kt&1)*SST)*2;
        tile_mma16<TERMS>(b, b+AL*2, b+BH*2, b+(BH+SB)*2, acc, wm, wn, lane);
        __syncthreads();
    }
#pragma unroll
    for(int mt=0;mt<4;mt++)
#pragma unroll
        for(int h=0;h<2;h++){
            int gr = bm + wm*64 + mt*16 + gid + h*8;
#pragma unroll
            for(int nt=0;nt<4;nt++){
                int gc = bn + wn*32 + nt*8 + tig*2;
                float2* p = (float2*)(C + (size_t)gr*N + gc);
                float2 v = make_float2(acc[mt][nt][h*2], acc[mt][nt][h*2+1]);
                if(MODE==1){ float2 o = *p; v.x += o.x; v.y += o.y; }
                *p = v;
            }
        }
}

// ------------------------- embedding gather --------------------------------
__global__ void embed_k(const int* __restrict__ tok, const float* __restrict__ emb){
    int i = blockIdx.x*256 + threadIdx.x;
    int t = i >> 8;
    int d = (i & 255) * 4;
    int id = tok[t];
    *(float4*)&g_h[(size_t)t*DIM + d] = *(const float4*)&emb[(size_t)id*DIM + d];
}

// ------------------------- rmsnorm: g_h -> g_xn + hi/lo planes -------------
__global__ void rms_k(const float* __restrict__ w){
    int t = blockIdx.x, tid = threadIdx.x;
    const float* xr = g_h + (size_t)t*DIM;
    float s = 0.f;
    for(int i = tid; i < DIM; i += 256){ float v = xr[i]; s += v*v; }
#pragma unroll
    for(int o=16;o;o>>=1) s += __shfl_xor_sync(0xffffffffu, s, o);
    __shared__ float sm[8];
    if((tid&31)==0) sm[tid>>5] = s;
    __syncthreads();
    if(tid==0){
        float tot = 0.f;
#pragma unroll
        for(int i=0;i<8;i++) tot += sm[i];
        sm[0] = rsqrtf(tot/DIM + EPSF);
    }
    __syncthreads();
    float inv = sm[0];
    float* o = g_xn + (size_t)t*DIM;
    for(int i = tid; i < DIM; i += 256){
        float v = xr[i]*inv*w[i];
        o[i] = v;
        __half hh = __float2half_rn(v);
        g_xh[(size_t)t*DIM + i] = hh;
        g_xl[(size_t)t*DIM + i] = __float2half_rn(v - __half2float(hh));
    }
}

// ------------------------- KV prep: fp32 qkv -> half planes (rope fused) ---
__global__ void kprep_k(){
    int i = blockIdx.x*256 + threadIdx.x;
    if(i >= NBATCH*NKV*(HD/4)*SEQ) return;
    int s  = i & (SEQ-1);
    int r  = i >> 11;
    int d4 = r & 15;
    int bk = r >> 4;
    int b = bk >> 2, kvh = bk & 3;
    float4 v = *(const float4*)(g_qkv + (size_t)(b*SEQ + s)*QKVD + 1024 + kvh*HD + d4*4);
    float2 rc0 = g_rt[s*32 + d4*2];
    float2 rc1 = g_rt[s*32 + d4*2 + 1];
    float vv[4];
    vv[0] = v.x*rc0.x - v.y*rc0.y;
    vv[1] = v.x*rc0.y + v.y*rc0.x;
    vv[2] = v.z*rc1.x - v.w*rc1.y;
    vv[3] = v.z*rc1.y + v.w*rc1.x;
#pragma unroll
    for(int c=0;c<4;c++){
        size_t d = ((size_t)bk*HD + d4*4 + c)*SEQ + s;
        __half hh = __float2half_rn(vv[c]);
        g_kth[d] = hh;
        g_ktl[d] = __float2half_rn(vv[c] - __half2float(hh));
    }
}
__global__ void vprep_k(){
    int i = blockIdx.x*256 + threadIdx.x;
    if(i >= NBATCH*NKV*SEQ*(HD/4)) return;
    int d4 = i & 15;
    int rs = i >> 4;
    int s  = rs & (SEQ-1);
    int bk = rs >> 11;
    int b = bk >> 2, kvh = bk & 3;
    float4 v = *(const float4*)(g_qkv + (size_t)(b*SEQ + s)*QKVD + 1280 + kvh*HD + d4*4);
    size_t d = (size_t)rs*HD + d4*4;
    unsigned h01, l01, h23, l23;
    split2u(v.x, v.y, h01, l01);
    split2u(v.z, v.w, h23, l23);
    *(unsigned*)&g_vh[d  ] = h01; *(unsigned*)&g_vh[d+2] = h23;
    *(unsigned*)&g_vl[d  ] = l01; *(unsigned*)&g_vl[d+2] = l23;
}

// ------------------------- tensor-core flash attention (rope fused) --------
#define FQ  (128*72)
#define FKV (64*72)
#define FSMEM ((2*FQ + 4*FKV)*2)
__global__ __launch_bounds__(256) void fattn_k(){
    extern __shared__ __half fsm[];
    __half* sQh = fsm;
    __half* sQl = fsm + FQ;
    __half* sKh = fsm + 2*FQ;
    __half* sKl = fsm + 2*FQ + FKV;
    __half* sVh = fsm + 2*FQ + 2*FKV;
    __half* sVl = fsm + 2*FQ + 3*FKV;
    const int qt = blockIdx.x, h = blockIdx.y, b = blockIdx.z;
    const int kvh = h >> 2;
    const int tid = threadIdx.x, wid = tid>>5, lane = tid&31;
    const int gid = lane>>2, tig = lane&3, l15 = lane&15, ahl = (lane>>4)<<3;
    unsigned uQh = (unsigned)__cvta_generic_to_shared(sQh);
    unsigned uQl = (unsigned)__cvta_generic_to_shared(sQl);
    unsigned uKh = (unsigned)__cvta_generic_to_shared(sKh);
    unsigned uKl = (unsigned)__cvta_generic_to_shared(sKl);
    unsigned uVh = (unsigned)__cvta_generic_to_shared(sVh);
    unsigned uVl = (unsigned)__cvta_generic_to_shared(sVl);

#pragma unroll
    for(int u=0;u<8;u++){
        int s = u*256 + tid;
        int r = s>>4, c4 = (s&15)*4;
        float4 v = *(const float4*)(g_qkv + (size_t)(b*SEQ + qt*128 + r)*QKVD + h*HD + c4);
        int seqpos = qt*128 + r;
        float2 rc0 = g_rt[seqpos*32 + (c4>>1)];
        float2 rc1 = g_rt[seqpos*32 + (c4>>1) + 1];
        float r0 = (v.x*rc0.x - v.y*rc0.y)*0.125f;
        float r1 = (v.x*rc0.y + v.y*rc0.x)*0.125f;
        float r2 = (v.z*rc1.x - v.w*rc1.y)*0.125f;
        float r3 = (v.z*rc1.y + v.w*rc1.x)*0.125f;
        unsigned h01,l01,h23,l23;
        split2u(r0,r1,h01,l01); split2u(r2,r3,h23,l23);
        *(unsigned*)&sQh[r*72+c4] = h01; *(unsigned*)&sQh[r*72+c4+2] = h23;
        *(unsigned*)&sQl[r*72+c4] = l01; *(unsigned*)&sQl[r*72+c4+2] = l23;
    }
    __syncthreads();
    unsigned qh[4][4], ql[4][4];
#pragma unroll
    for(int ks=0;ks<4;ks++){
        unsigned aoff = (unsigned)((wid*16 + l15)*72 + ks*16 + ahl)*2;
        ldsm4(qh[ks], uQh + aoff);
        ldsm4(ql[ks], uQl + aoff);
    }

    float o[8][4];
#pragma unroll
    for(int j=0;j<8;j++){ o[j][0]=0.f; o[j][1]=0.f; o[j][2]=0.f; o[j][3]=0.f; }
    float m0=-1e30f, m1=-1e30f, l0=0.f, l1=0.f;

    const int jmax = 2*qt + 1;
    for(int jt=0;jt<=jmax;jt++){
        __syncthreads();
#pragma unroll
        for(int u=0;u<2;u++){
            int s = u*256 + tid;
            int r = s>>3, c8 = (s&7)*8;
            size_t kg = ((size_t)(b*NKV+kvh)*HD + r)*SEQ + jt*64 + c8;
            *(uint4*)&sKh[r*72+c8] = *(const uint4*)(g_kth + kg);
            *(uint4*)&sKl[r*72+c8] = *(const uint4*)(g_ktl + kg);
            size_t vg = ((size_t)(b*NKV+kvh)*SEQ + jt*64 + r)*HD + c8;
            *(uint4*)&sVh[r*72+c8] = *(const uint4*)(g_vh + vg);
            *(uint4*)&sVl[r*72+c8] = *(const uint4*)(g_vl + vg);
        }
        __syncthreads();

        float sc[8][4];
#pragma unroll
        for(int j=0;j<8;j++){ sc[j][0]=0.f; sc[j][1]=0.f; sc[j][2]=0.f; sc[j][3]=0.f; }
#pragma unroll
        for(int j=0;j<8;j++){
#pragma unroll
            for(int ks=0;ks<4;ks++){
                unsigned kbh[2], kbl[2];
                unsigned boff = (unsigned)((ks*16 + l15)*72 + j*8)*2;
                ldsm2t(kbh, uKh + boff);
                ldsm2t(kbl, uKl + boff);
                mma16816(sc[j], qh[ks], kbh);
                mma16816(sc[j], ql[ks], kbh);
                mma16816(sc[j], qh[ks], kbl);
            }
        }
        if(jt >= 2*qt){
            int q0 = qt*128 + wid*16 + gid;
#pragma unroll
            for(int j=0;j<8;j++){
                int c = jt*64 + j*8 + tig*2;
                if(c   > q0  ) sc[j][0] = -1e30f;
                if(c+1 > q0  ) sc[j][1] = -1e30f;
                if(c   > q0+8) sc[j][2] = -1e30f;
                if(c+1 > q0+8) sc[j][3] = -1e30f;
            }
        }
        float mv0=-1e30f, mv1=-1e30f;
#pragma unroll
        for(int j=0;j<8;j++){
            mv0 = fmaxf(mv0, fmaxf(sc[j][0], sc[j][1]));
            mv1 = fmaxf(mv1, fmaxf(sc[j][2], sc[j][3]));
        }
        mv0 = fmaxf(mv0, __shfl_xor_sync(0xffffffffu, mv0, 1));
        mv0 = fmaxf(mv0, __shfl_xor_sync(0xffffffffu, mv0, 2));
        mv1 = fmaxf(mv1, __shfl_xor_sync(0xffffffffu, mv1, 1));
        mv1 = fmaxf(mv1, __shfl_xor_sync(0xffffffffu, mv1, 2));
        float mn0 = fmaxf(m0, mv0), mn1 = fmaxf(m1, mv1);
        float f0 = __expf(m0 - mn0), f1 = __expf(m1 - mn1);
        float rs0 = 0.f, rs1 = 0.f;
#pragma unroll
        for(int j=0;j<8;j++){
            sc[j][0] = __expf(sc[j][0]-mn0); rs0 += sc[j][0];
            sc[j][1] = __expf(sc[j][1]-mn0); rs0 += sc[j][1];
            sc[j][2] = __expf(sc[j][2]-mn1); rs1 += sc[j][2];
            sc[j][3] = __expf(sc[j][3]-mn1); rs1 += sc[j][3];
        }
        rs0 += __shfl_xor_sync(0xffffffffu, rs0, 1);
        rs0 += __shfl_xor_sync(0xffffffffu, rs0, 2);
        rs1 += __shfl_xor_sync(0xffffffffu, rs1, 1);
        rs1 += __shfl_xor_sync(0xffffffffu, rs1, 2);
        l0 = l0*f0 + rs0;  l1 = l1*f1 + rs1;
        m0 = mn0;  m1 = mn1;
#pragma unroll
        for(int j=0;j<8;j++){
            o[j][0]*=f0; o[j][1]*=f0; o[j][2]*=f1; o[j][3]*=f1;
        }
        unsigned ph[4][4], pl[4][4];
#pragma unroll
        for(int ks=0;ks<4;ks++){
            split2u(sc[2*ks  ][0], sc[2*ks  ][1], ph[ks][0], pl[ks][0]);
            split2u(sc[2*ks  ][2], sc[2*ks  ][3], ph[ks][1], pl[ks][1]);
            split2u(sc[2*ks+1][0], sc[2*ks+1][1], ph[ks][2], pl[ks][2]);
            split2u(sc[2*ks+1][2], sc[2*ks+1][3], ph[ks][3], pl[ks][3]);
        }
#pragma unroll
        for(int j=0;j<8;j++){
#pragma unroll
            for(int ks=0;ks<4;ks++){
                unsigned vbh[2], vbl[2];
                unsigned boff = (unsigned)((ks*16 + l15)*72 + j*8)*2;
                ldsm2t(vbh, uVh + boff);
                ldsm2t(vbl, uVl + boff);
                mma16816(o[j], ph[ks], vbh);
                mma16816(o[j], pl[ks], vbh);
                mma16816(o[j], ph[ks], vbl);
            }
        }
    }
    float i0 = 1.f/l0, i1 = 1.f/l1;
    size_t t0 = (size_t)(b*SEQ + qt*128 + wid*16 + gid);
#pragma unroll
    for(int j=0;j<8;j++){
        int col = h*HD + j*8 + tig*2;
        unsigned hh, ll;
        split2u(o[j][0]*i0, o[j][1]*i0, hh, ll);
        *(unsigned*)&g_xh[t0*DIM + col] = hh;
        *(unsigned*)&g_xl[t0*DIM + col] = ll;
        split2u(o[j][2]*i1, o[j][3]*i1, hh, ll);
        *(unsigned*)&g_xh[(t0+8)*DIM + col] = hh;
        *(unsigned*)&g_xl[(t0+8)*DIM + col] = ll;
    }
}

// ------------------------- MoE routing -------------------------------------
__global__ void zero_k(){
    int i = threadIdx.x;
    if(i < NE){ g_cnt[i]=0; g_scnt[i]=0; }
}

__global__ void route_k(const float* __restrict__ gw){
    int warp = threadIdx.x>>5, lane = threadIdx.x&31;
    int t = blockIdx.x*8 + warp;
    float acc[NE];
#pragma unroll
    for(int e=0;e<NE;e++) acc[e]=0.f;
    const float* xr = g_xn + (size_t)t*DIM;
    for(int i=lane;i<DIM;i+=32){
        float xv = xr[i];
        const float* g = gw + (size_t)i*NE;
#pragma unroll
        for(int e=0;e<NE;e++) acc[e] += xv*g[e];
    }
#pragma unroll
    for(int e=0;e<NE;e++)
#pragma unroll
        for(int o=16;o;o>>=1) acc[e] += __shfl_xor_sync(0xffffffffu, acc[e], o);
    if(lane==0){
        float mx = acc[0];
#pragma unroll
        for(int e=1;e<NE;e++) mx = fmaxf(mx, acc[e]);
        float p[NE];
#pragma unroll
        for(int e=0;e<NE;e++) p[e] = __expf(acc[e]-mx);
        int e0=0;
#pragma unroll
        for(int e=1;e<NE;e++) if(p[e] > p[e0]) e0=e;
        int e1 = (e0==0)?1:0;
#pragma unroll
        for(int e=0;e<NE;e++) if(e!=e0 && p[e] > p[e1]) e1=e;
        float w0=p[e0], w1=p[e1], ws=w0+w1;
        g_tope[t*2]=e0; g_tope[t*2+1]=e1;
        g_topw[t*2]=w0/ws; g_topw[t*2+1]=w1/ws;
        atomicAdd(&g_cnt[e0],1); atomicAdd(&g_cnt[e1],1);
    }
}

__global__ void build_k(){
    if(threadIdx.x || blockIdx.x) return;
    int s=0, nt=0;
    for(int e=0;e<NE;e++){
        g_seg[e]=s;
        int c = g_cnt[e];
        int tiles = (c+127)>>7;
        for(int t2=0;t2<tiles;t2++){
            g_te[nt]=e; g_tp[nt]=s+t2*128;
            int v = c - t2*128;
            g_tv[nt] = v>128 ? 128 : v;
            nt++;
        }
        s += c;
    }
    for(; nt<MAXT; nt++) g_tv[nt]=0;
}

__global__ void scatter_k(){
    int t = blockIdx.x*256 + threadIdx.x;
    if(t >= TT) return;
#pragma unroll
    for(int j=0;j<2;j++){
        int e = g_tope[t*2+j];
        int pos = g_seg[e] + atomicAdd(&g_scnt[e],1);
        g_perm[pos]=t; g_pwgt[pos]=g_topw[t*2+j];
    }
}

// ------------------------- gathered pipelined GEMM: x @ w1 / w3 ------------
// FUSE=0: write fp32 to g_b1.  FUSE=1 (w3 pass): read g_b1, out = silu(b1)*acc,
// hi/lo-split and write g_ah/g_al (separate planes — no aliasing with g_xh/g_xl).
template<int TERMS, int FUSE>
__global__ __launch_bounds__(256) void tmoe13_k(int bid, size_t lbase){
    extern __shared__ __half smp[];
    int tile = blockIdx.y;
    int valid = g_tv[tile];
    if(valid==0) return;
    int e = g_te[tile], p0 = g_tp[tile];
    size_t boff = lbase + (size_t)e*DIM*HID;
    const __half* Bhg = whsel(bid)   + boff;
    const __half* Blg = whsel(bid+1) + boff;
    __shared__ int rowtok[128];
    const int tid = threadIdx.x;
    const int bn = blockIdx.x*128;
    if(tid < 128) rowtok[tid] = (tid < valid) ? g_perm[p0+tid] : -1;
    __syncthreads();
    const int warp = tid>>5, lane = tid&31;
    const int wm = warp>>2, wn = warp&3, gid = lane>>2, tig = lane&3;
    const int SST = (TERMS==3) ? (2*SA+2*SB) : (2*SA+SB);
    unsigned u0 = (unsigned)__cvta_generic_to_shared(smp);
    float acc[4][4][4];
#pragma unroll
    for(int i=0;i<4;i++)
#pragma unroll
        for(int j=0;j<4;j++)
#pragma unroll
            for(int q=0;q<4;q++) acc[i][j][q]=0.f;

    auto loadSt = [&](int st, int k0){
        unsigned b = u0 + (unsigned)(st*SST)*2;
#pragma unroll
        for(int u=0;u<2;u++){
            int s = u*256+tid, r = s>>2, c8 = (s&3)*8;
            int tk = rowtok[r];
            unsigned pr = (tk>=0) ? 16u : 0u;
            size_t g = (size_t)(tk>=0 ? tk : 0)*DIM + k0 + c8;
            cpa16(b + (unsigned)(r*AST+c8)*2,      g_xh + g, pr);
            cpa16(b + (unsigned)(SA + r*AST+c8)*2, g_xl + g, pr);
        }
#pragma unroll
        for(int u=0;u<2;u++){
            int s = u*256+tid, kr = s>>4, c8 = (s&15)*8;
            size_t g = (size_t)(k0+kr)*HID + bn + c8;
            cpa16(b + (unsigned)(2*SA + kr*BST + c8)*2,    Bhg + g, 16);
            if(TERMS==3)
                cpa16(b + (unsigned)(2*SA+SB + kr*BST + c8)*2, Blg + g, 16);
        }
        cpa_commit();
    };

    const int NT = DIM/BK;
    loadSt(0, 0);
    for(int kt=0; kt<NT; kt++){
        if(kt+1 < NT){ loadSt((kt+1)&1, (kt+1)*BK); cpa_wait<1>(); }
        else         { cpa_wait<0>(); }
        __syncthreads();
        unsigned b = u0 + (unsigned)((kt&1)*SST)*2;
        tile_mma16<TERMS>(b, b+SA*2, b+2*SA*2, b+(2*SA+SB)*2, acc, wm, wn, lane);
        __syncthreads();
    }
#pragma unroll
    for(int mt=0;mt<4;mt++)
#pragma unroll
        for(int h=0;h<2;h++){
            int lr = wm*64 + mt*16 + gid + h*8;
            if(lr >= valid) continue;
            size_t rowoff = (size_t)(p0+lr)*HID + bn;
#pragma unroll
            for(int nt=0;nt<4;nt++){
                int lc = wn*32 + nt*8 + tig*2;
                if(FUSE==0){
                    *(float2*)(g_b1 + rowoff + lc) =
                        make_float2(acc[mt][nt][h*2], acc[mt][nt][h*2+1]);
                } else {
                    float2 b1v = *(const float2*)(g_b1 + rowoff + lc);
                    float ra = b1v.x/(1.f+__expf(-b1v.x)) * acc[mt][nt][h*2];
                    float rb = b1v.y/(1.f+__expf(-b1v.y)) * acc[mt][nt][h*2+1];
                    unsigned hh, ll;
                    split2u(ra, rb, hh, ll);
                    *(unsigned*)&g_ah[rowoff + lc] = hh;
                    *(unsigned*)&g_al[rowoff + lc] = ll;
                }
            }
        }
}

// ------------------------- act @ w2, weighted scatter-add into g_h ---------
template<int TERMS>
__global__ __launch_bounds__(256) void tmoe2_k(int bid, size_t lbase){
    extern __shared__ __half smp[];
    int tile = blockIdx.y;
    int valid = g_tv[tile];
    if(valid==0) return;
    int e = g_te[tile], p0 = g_tp[tile];
    size_t boff = lbase + (size_t)e*HID*DIM;
    const __half* Bhg = whsel(bid)   + boff;
    const __half* Blg = whsel(bid+1) + boff;
    const int tid = threadIdx.x;
    const int bn = blockIdx.x*128;
    const int warp = tid>>5, lane = tid&31;
    const int wm = warp>>2, wn = warp&3, gid = lane>>2, tig = lane&3;
    const int SST = (TERMS==3) ? (2*SA+2*SB) : (2*SA+SB);
    unsigned u0 = (unsigned)__cvta_generic_to_shared(smp);
    float acc[4][4][4];
#pragma unroll
    for(int i=0;i<4;i++)
#pragma unroll
        for(int j=0;j<4;j++)
#pragma unroll
            for(int q=0;q<4;q++) acc[i][j][q]=0.f;

    auto loadSt = [&](int st, int k0){
        unsigned b = u0 + (unsigned)(st*SST)*2;
#pragma unroll
        for(int u=0;u<2;u++){
            int s = u*256+tid, r = s>>2, c8 = (s&3)*8;
            unsigned pr = (r<valid) ? 16u : 0u;
            size_t g = (size_t)(p0 + (r<valid ? r : 0))*HID + k0 + c8;
            cpa16(b + (unsigned)(r*AST+c8)*2,      g_ah + g, pr);
            cpa16(b + (unsigned)(SA + r*AST+c8)*2, g_al + g, pr);
        }
#pragma unroll
        for(int u=0;u<2;u++){
            int s = u*256+tid, kr = s>>4, c8 = (s&15)*8;
            size_t g = (size_t)(k0+kr)*DIM + bn + c8;
            cpa16(b + (unsigned)(2*SA + kr*BST + c8)*2,    Bhg + g, 16);
            if(TERMS==3)
                cpa16(b + (unsigned)(2*SA+SB + kr*BST + c8)*2, Blg + g, 16);
        }
        cpa_commit();
    };

    const int NT = HID/BK;
    loadSt(0, 0);
    for(int kt=0; kt<NT; kt++){
        if(kt+1 < NT){ loadSt((kt+1)&1, (kt+1)*BK); cpa_wait<1>(); }
        else         { cpa_wait<0>(); }
        __syncthreads();
        unsigned b = u0 + (unsigned)((kt&1)*SST)*2;
        tile_mma16<TERMS>(b, b+SA*2, b+2*SA*2, b+(2*SA+SB)*2, acc, wm, wn, lane);
        __syncthreads();
    }
#pragma unroll
    for(int mt=0;mt<4;mt++)
#pragma unroll
        for(int h=0;h<2;h++){
            int lr = wm*64 + mt*16 + gid + h*8;
            if(lr >= valid) continue;
            int p  = p0 + lr;
            int tk = g_perm[p];
            float wf = g_pwgt[p];
            float* hrow = g_h + (size_t)tk*DIM + bn;
#pragma unroll
            for(int nt=0;nt<4;nt++){
                int lc = wn*32 + nt*8 + tig*2;
                atomicAdd(&hrow[lc  ], wf*acc[mt][nt][h*2  ]);
                atomicAdd(&hrow[lc+1], wf*acc[mt][nt][h*2+1]);
            }
        }
}

// ------------------------- host orchestration ------------------------------
extern "C" void kernel_launch(void* const* d_in, const int* in_sizes, int n_in,
                              void* d_out, int out_size)
{
    const int*   tokens    = (const int*)  d_in[0];
    const int*   sp        = (const int*)  d_in[1];
    const float* tok_emb   = (const float*)d_in[2];
    const float* attn_norm = (const float*)d_in[3];
    const float* wq        = (const float*)d_in[4];
    const float* wk        = (const float*)d_in[5];
    const float* wv        = (const float*)d_in[6];
    const float* wo        = (const float*)d_in[7];
    const float* ffn_norm  = (const float*)d_in[8];
    const float* gate      = (const float*)d_in[9];
    const float* w1        = (const float*)d_in[10];
    const float* w2        = (const float*)d_in[11];
    const float* w3        = (const float*)d_in[12];
    const float* normw     = (const float*)d_in[13];
    const float* outw      = (const float*)d_in[14];
    float* out = (float*)d_out;

    const int SM3 = (2*SA+2*SB)*2*2;   /* 75776 B */
    const int SM2 = (2*SA+SB)*2*2;     /* 58368 B */
    const int SM1 = (SA+SB)*2*2;       /* 37888 B */
    cudaFuncSetAttribute(hgemm_k<0,3>,   cudaFuncAttributeMaxDynamicSharedMemorySize, SM3);
    cudaFuncSetAttribute(hgemm_k<1,3>,   cudaFuncAttributeMaxDynamicSharedMemorySize, SM3);
    cudaFuncSetAttribute(hgemm_k<0,1>,   cudaFuncAttributeMaxDynamicSharedMemorySize, SM1);
    cudaFuncSetAttribute((const void*)tmoe13_k<3,0>, cudaFuncAttributeMaxDynamicSharedMemorySize, SM3);
    cudaFuncSetAttribute((const void*)tmoe13_k<3,1>, cudaFuncAttributeMaxDynamicSharedMemorySize, SM3);
    cudaFuncSetAttribute((const void*)tmoe13_k<2,0>, cudaFuncAttributeMaxDynamicSharedMemorySize, SM2);
    cudaFuncSetAttribute((const void*)tmoe13_k<2,1>, cudaFuncAttributeMaxDynamicSharedMemorySize, SM2);
    cudaFuncSetAttribute(tmoe2_k<3>,     cudaFuncAttributeMaxDynamicSharedMemorySize, SM3);
    cudaFuncSetAttribute(tmoe2_k<2>,     cudaFuncAttributeMaxDynamicSharedMemorySize, SM2);
    cudaFuncSetAttribute(fattn_k,        cudaFuncAttributeMaxDynamicSharedMemorySize, FSMEM);

    // ---- weight prep (hi/lo fp16 planes; logits hi-only) + rope table ----
    {
        int n4;
        n4 = NL*DIM*DIM/4;     cvtpack_k<<<(n4+255)/256,256>>>(wq, DIM,  0,    n4);
        n4 = NL*DIM*KVD/4;     cvtpack_k<<<(n4+255)/256,256>>>(wk, KVD,  1024, n4);
        n4 = NL*DIM*KVD/4;     cvtpack_k<<<(n4+255)/256,256>>>(wv, KVD,  1280, n4);
        n4 = NL*DIM*DIM/4;     cvt_k<<<(n4+255)/256,256>>>(wo,   6, 7,  n4);
        n4 = NL*NE*DIM*HID/4;  cvt_k<<<(n4+255)/256,256>>>(w1,   8, 9,  n4);
        n4 = NL*NE*DIM*HID/4;  cvt_k<<<(n4+255)/256,256>>>(w3,  10, 11, n4);
        n4 = NL*NE*HID*DIM/4;  cvt_k<<<(n4+255)/256,256>>>(w2,  12, 13, n4);
        n4 = DIM*VOCAB/4;      cvthi_k<<<(n4+255)/256,256>>>(outw, 14, n4);
        ropetab_k<<<(SEQ*32+255)/256,256>>>(sp);
    }

    embed_k<<<TT*(DIM/4)/256, 256>>>(tokens, tok_emb);

    const int nkv4 = NBATCH*NKV*(HD/4)*SEQ;

    for(int l=0;l<NL;l++){
        size_t lqkv = (size_t)l*DIM*QKVD, lq = (size_t)l*DIM*DIM;
        size_t l13 = (size_t)l*NE*DIM*HID, l2 = (size_t)l*NE*HID*DIM;

        rms_k<<<TT,256>>>(attn_norm + (size_t)l*DIM);
        hgemm_k<0,3><<<dim3(QKVD/128, TT/128), 256, SM3>>>(0, lqkv, nullptr, 2, QKVD, DIM);
        kprep_k<<<(nkv4+255)/256, 256>>>();
        vprep_k<<<(nkv4+255)/256, 256>>>();
        fattn_k<<<dim3(SEQ/128, NH, NBATCH), 256, FSMEM>>>();
        hgemm_k<1,3><<<dim3(DIM/128, TT/128), 256, SM3>>>(6, lq, nullptr, 0, DIM, DIM);

        rms_k<<<TT,256>>>(ffn_norm + (size_t)l*DIM);
        zero_k<<<1,32>>>();
        route_k<<<TT/8,256>>>(gate + (size_t)l*DIM*NE);
        build_k<<<1,1>>>();
        scatter_k<<<TT/256,256>>>();
        if(l == 0){
            tmoe13_k<3,0><<<dim3(HID/128, MAXT), 256, SM3>>>(8,  l13);
            tmoe13_k<3,1><<<dim3(HID/128, MAXT), 256, SM3>>>(10, l13);
            tmoe2_k<3><<<dim3(DIM/128, MAXT), 256, SM3>>>(12, l2);
        } else {
            tmoe13_k<2,0><<<dim3(HID/128, MAXT), 256, SM2>>>(8,  l13);
            tmoe13_k<2,1><<<dim3(HID/128, MAXT), 256, SM2>>>(10, l13);
            tmoe2_k<2><<<dim3(DIM/128, MAXT), 256, SM2>>>(12, l2);
        }
    }

    rms_k<<<TT,256>>>(normw);
    hgemm_k<0,1><<<dim3(VOCAB/128, TT/128), 256, SM1>>>(14, 0, out, -1, VOCAB, DIM);
}